// round 2
// baseline (speedup 1.0000x reference)
#include <cuda_runtime.h>
#include <math.h>
#include <stdint.h>

#define B_  4
#define T_  1024
#define E_  1024
#define H_  16
#define HD  64
#define L_  6
#define FF_ 4096
#define V_  32000
#define BT  (B_ * T_)

// ---------------- device scratch (static, no allocations) ----------------
__device__ float g_x[BT * E_];
__device__ float g_q[BT * E_];
__device__ float g_k[BT * E_];
__device__ float g_v[BT * E_];
__device__ float g_attn[BT * E_];
__device__ float g_tmp[BT * E_];
__device__ float g_ff[(size_t)BT * FF_];
__device__ float g_scores[(size_t)B_ * H_ * T_ * T_];   // 256 MiB

// ---------------- warp/block reductions ----------------
__device__ __forceinline__ float warpSum(float v) {
    #pragma unroll
    for (int o = 16; o > 0; o >>= 1) v += __shfl_xor_sync(0xffffffffu, v, o);
    return v;
}
__device__ __forceinline__ float warpMax(float v) {
    #pragma unroll
    for (int o = 16; o > 0; o >>= 1) v = fmaxf(v, __shfl_xor_sync(0xffffffffu, v, o));
    return v;
}

// ---------------- embedding: x[b,t,:] = tok[idx[b,t],:] + pos[t,:] ----------------
__global__ void embed_kernel(const int* __restrict__ idx,
                             const float* __restrict__ tok,
                             const float* __restrict__ pos,
                             float* __restrict__ x) {
    int bt = blockIdx.x;
    int t  = bt & (T_ - 1);
    int id = idx[bt];
    int c  = threadIdx.x;                 // 256 threads, float4 each = 1024 floats
    float4 a = ((const float4*)(tok + (size_t)id * E_))[c];
    float4 p = ((const float4*)(pos + (size_t)t  * E_))[c];
    a.x += p.x; a.y += p.y; a.z += p.z; a.w += p.w;
    ((float4*)(x + (size_t)bt * E_))[c] = a;
}

// ---------------- SGEMM: C = A(MxK) * B(KxN) + bias, optional ReLU ----------------
// Requires: M%128==0, N%128==0, K%16==0 (true for all shapes used here).
template<bool RELU>
__global__ __launch_bounds__(256, 2)
void sgemm_kernel(const float* __restrict__ A, const float* __restrict__ B,
                  const float* __restrict__ bias, float* __restrict__ C,
                  int M, int N, int K) {
    __shared__ float As[16][128];   // transposed: As[k][m]
    __shared__ float Bs[16][128];   // Bs[k][n]
    int tid = threadIdx.x;
    int tx = tid & 15, ty = tid >> 4;
    int bm = blockIdx.y * 128, bn = blockIdx.x * 128;

    const float* Ab = A + (size_t)bm * K;
    const float* Bb = B + bn;

    int arow = tid >> 2;            // 0..63
    int acol = (tid & 3) * 4;       // 0,4,8,12
    int brow = tid >> 5;            // 0..7
    int bcol = (tid & 31) * 4;      // 0..124

    float acc[8][8];
    #pragma unroll
    for (int i = 0; i < 8; i++)
        #pragma unroll
        for (int j = 0; j < 8; j++) acc[i][j] = 0.f;

    for (int k0 = 0; k0 < K; k0 += 16) {
        #pragma unroll
        for (int rr = 0; rr < 2; rr++) {
            float4 a = *(const float4*)(Ab + (size_t)(arow + rr * 64) * K + k0 + acol);
            As[acol + 0][arow + rr * 64] = a.x;
            As[acol + 1][arow + rr * 64] = a.y;
            As[acol + 2][arow + rr * 64] = a.z;
            As[acol + 3][arow + rr * 64] = a.w;
        }
        #pragma unroll
        for (int rr = 0; rr < 2; rr++) {
            float4 b4 = *(const float4*)(Bb + (size_t)(k0 + brow + rr * 8) * N + bcol);
            *(float4*)&Bs[brow + rr * 8][bcol] = b4;
        }
        __syncthreads();

        #pragma unroll
        for (int k = 0; k < 16; k++) {
            float ra[8], rb[8];
            *(float4*)&ra[0] = *(const float4*)&As[k][ty * 8];
            *(float4*)&ra[4] = *(const float4*)&As[k][ty * 8 + 4];
            *(float4*)&rb[0] = *(const float4*)&Bs[k][tx * 8];
            *(float4*)&rb[4] = *(const float4*)&Bs[k][tx * 8 + 4];
            #pragma unroll
            for (int i = 0; i < 8; i++)
                #pragma unroll
                for (int j = 0; j < 8; j++)
                    acc[i][j] = fmaf(ra[i], rb[j], acc[i][j]);
        }
        __syncthreads();
    }

    #pragma unroll
    for (int i = 0; i < 8; i++) {
        int row = bm + ty * 8 + i;
        #pragma unroll
        for (int j = 0; j < 8; j += 4) {
            int col = bn + tx * 8 + j;
            float4 v;
            v.x = acc[i][j]; v.y = acc[i][j + 1]; v.z = acc[i][j + 2]; v.w = acc[i][j + 3];
            v.x += bias[col]; v.y += bias[col + 1]; v.z += bias[col + 2]; v.w += bias[col + 3];
            if (RELU) {
                v.x = fmaxf(v.x, 0.f); v.y = fmaxf(v.y, 0.f);
                v.z = fmaxf(v.z, 0.f); v.w = fmaxf(v.w, 0.f);
            }
            *(float4*)(C + (size_t)row * N + col) = v;
        }
    }
}

// ---------------- attention scores: S[bh,i,j] = dot(Q,K)/8, causal ----------------
// grid (jt=16, it=16, bh=64), block 256. Only jt<=it tiles computed.
__global__ void attn_scores_kernel(const float* __restrict__ Q,
                                   const float* __restrict__ Kb,
                                   float* __restrict__ S) {
    int jt = blockIdx.x, it = blockIdx.y, bh = blockIdx.z;
    if (jt > it) return;
    int b = bh >> 4, h = bh & 15;

    __shared__ float Qs[64][65];
    __shared__ float Ks[64][65];
    int tid = threadIdx.x;
    #pragma unroll
    for (int p = 0; p < 4; p++) {
        int r = p * 16 + (tid >> 4);
        int c = (tid & 15) * 4;
        float4 qv = *(const float4*)(Q + ((size_t)(b * T_ + it * 64 + r) * E_) + h * HD + c);
        Qs[r][c] = qv.x; Qs[r][c + 1] = qv.y; Qs[r][c + 2] = qv.z; Qs[r][c + 3] = qv.w;
        float4 kv = *(const float4*)(Kb + ((size_t)(b * T_ + jt * 64 + r) * E_) + h * HD + c);
        Ks[r][c] = kv.x; Ks[r][c + 1] = kv.y; Ks[r][c + 2] = kv.z; Ks[r][c + 3] = kv.w;
    }
    __syncthreads();

    int tx = tid & 15, ty = tid >> 4;
    float acc[4][4] = {};
    #pragma unroll 8
    for (int d = 0; d < 64; d++) {
        float rq[4], rk[4];
        #pragma unroll
        for (int ii = 0; ii < 4; ii++) rq[ii] = Qs[ty * 4 + ii][d];
        #pragma unroll
        for (int jj = 0; jj < 4; jj++) rk[jj] = Ks[tx * 4 + jj][d];
        #pragma unroll
        for (int ii = 0; ii < 4; ii++)
            #pragma unroll
            for (int jj = 0; jj < 4; jj++)
                acc[ii][jj] = fmaf(rq[ii], rk[jj], acc[ii][jj]);
    }

    #pragma unroll
    for (int ii = 0; ii < 4; ii++) {
        int ig = it * 64 + ty * 4 + ii;
        #pragma unroll
        for (int jj = 0; jj < 4; jj++) {
            int jg = jt * 64 + tx * 4 + jj;
            float v = acc[ii][jj] * 0.125f;          // 1/sqrt(64)
            if (jg > ig) v = -1e30f;
            S[((size_t)bh * T_ + ig) * T_ + jg] = v;
        }
    }
}

// ---------------- row softmax over j <= i (in place) ----------------
__global__ void softmax_kernel(float* __restrict__ S) {
    int rid = blockIdx.x;
    int bh = rid >> 10, i = rid & 1023;
    float* row = S + ((size_t)bh * T_ + i) * T_;
    int n = i + 1;
    int t = threadIdx.x;                   // 128 threads

    float vals[8];
    float m = -1e30f;
    #pragma unroll
    for (int k = 0; k < 8; k++) {
        int j = t + k * 128;
        vals[k] = (j < n) ? row[j] : -1e30f;
        m = fmaxf(m, vals[k]);
    }
    __shared__ float sh[8];
    m = warpMax(m);
    int w = t >> 5, lane = t & 31;
    if (lane == 0) sh[w] = m;
    __syncthreads();
    if (w == 0) {
        float a = (lane < 4) ? sh[lane] : -1e30f;
        a = warpMax(a);
        if (lane == 0) sh[0] = a;
    }
    __syncthreads();
    float M = sh[0];

    float s = 0.f;
    #pragma unroll
    for (int k = 0; k < 8; k++) {
        int j = t + k * 128;
        if (j < n) { vals[k] = expf(vals[k] - M); s += vals[k]; }
    }
    __syncthreads();
    s = warpSum(s);
    if (lane == 0) sh[w] = s;
    __syncthreads();
    if (w == 0) {
        float a = (lane < 4) ? sh[lane] : 0.f;
        a = warpSum(a);
        if (lane == 0) sh[0] = a;
    }
    __syncthreads();
    float inv = 1.f / sh[0];

    #pragma unroll
    for (int k = 0; k < 8; k++) {
        int j = t + k * 128;
        if (j < n) row[j] = vals[k] * inv;
    }
}

// ---------------- O[b,i,h,:] = sum_j P[bh,i,j] V[b,j,h,:] ----------------
// grid (it=16, bh=64), block 256; loops jt = 0..it (triangular).
__global__ void attn_av_kernel(const float* __restrict__ S,
                               const float* __restrict__ Vb,
                               float* __restrict__ O) {
    int it = blockIdx.x, bh = blockIdx.y;
    int b = bh >> 4, h = bh & 15;
    __shared__ float Ps[64][65];
    __shared__ float Vs[64][65];
    int tid = threadIdx.x;
    int tx = tid & 15, ty = tid >> 4;
    float acc[4][4] = {};

    for (int jt = 0; jt <= it; jt++) {
        #pragma unroll
        for (int p = 0; p < 4; p++) {
            int r = p * 16 + (tid >> 4);
            int c = (tid & 15) * 4;
            int ig = it * 64 + r;
            int jg = jt * 64 + c;
            float4 s4 = *(const float4*)(S + ((size_t)bh * T_ + ig) * T_ + jg);
            Ps[r][c + 0] = (jg + 0 <= ig) ? s4.x : 0.f;
            Ps[r][c + 1] = (jg + 1 <= ig) ? s4.y : 0.f;
            Ps[r][c + 2] = (jg + 2 <= ig) ? s4.z : 0.f;
            Ps[r][c + 3] = (jg + 3 <= ig) ? s4.w : 0.f;
            float4 vv = *(const float4*)(Vb + ((size_t)(b * T_ + jt * 64 + r) * E_) + h * HD + c);
            Vs[r][c] = vv.x; Vs[r][c + 1] = vv.y; Vs[r][c + 2] = vv.z; Vs[r][c + 3] = vv.w;
        }
        __syncthreads();
        #pragma unroll 8
        for (int j = 0; j < 64; j++) {
            float rp[4], rv[4];
            #pragma unroll
            for (int ii = 0; ii < 4; ii++) rp[ii] = Ps[ty * 4 + ii][j];
            #pragma unroll
            for (int jj = 0; jj < 4; jj++) rv[jj] = Vs[j][tx * 4 + jj];
            #pragma unroll
            for (int ii = 0; ii < 4; ii++)
                #pragma unroll
                for (int jj = 0; jj < 4; jj++)
                    acc[ii][jj] = fmaf(rp[ii], rv[jj], acc[ii][jj]);
        }
        __syncthreads();
    }

    #pragma unroll
    for (int ii = 0; ii < 4; ii++) {
        int ig = it * 64 + ty * 4 + ii;
        #pragma unroll
        for (int jj = 0; jj < 4; jj++)
            O[((size_t)(b * T_ + ig)) * E_ + h * HD + tx * 4 + jj] = acc[ii][jj];
    }
}

// ---------------- out = LayerNorm(in (+ res)) * g + b ----------------
__global__ void add_ln_kernel(const float* __restrict__ in,
                              const float* __restrict__ res,    // nullable
                              const float* __restrict__ g,
                              const float* __restrict__ bb,
                              float* __restrict__ out) {
    int row = blockIdx.x;
    int t = threadIdx.x;                        // 256 threads * float4 = 1024
    float4 v = ((const float4*)(in + (size_t)row * E_))[t];
    if (res) {
        float4 r = ((const float4*)(res + (size_t)row * E_))[t];
        v.x += r.x; v.y += r.y; v.z += r.z; v.w += r.w;
    }
    float s  = v.x + v.y + v.z + v.w;
    float s2 = v.x * v.x + v.y * v.y + v.z * v.z + v.w * v.w;

    __shared__ float sh[16];
    s = warpSum(s); s2 = warpSum(s2);
    int w = t >> 5, lane = t & 31;
    if (lane == 0) { sh[w] = s; sh[w + 8] = s2; }
    __syncthreads();
    if (w == 0) {
        float a  = (lane < 8) ? sh[lane] : 0.f;
        a = warpSum(a);
        float a2 = (lane < 8) ? sh[lane + 8] : 0.f;
        a2 = warpSum(a2);
        if (lane == 0) { sh[0] = a; sh[8] = a2; }
    }
    __syncthreads();
    float mean = sh[0] * (1.f / E_);
    float var  = sh[8] * (1.f / E_) - mean * mean;
    float rstd = rsqrtf(var + 1e-5f);

    float4 gv = ((const float4*)g)[t];
    float4 bv = ((const float4*)bb)[t];
    float4 o;
    o.x = (v.x - mean) * rstd * gv.x + bv.x;
    o.y = (v.y - mean) * rstd * gv.y + bv.y;
    o.z = (v.z - mean) * rstd * gv.z + bv.z;
    o.w = (v.w - mean) * rstd * gv.w + bv.w;
    ((float4*)(out + (size_t)row * E_))[t] = o;
}

// ---------------- host launch ----------------
extern "C" void kernel_launch(void* const* d_in, const int* in_sizes, int n_in,
                              void* d_out, int out_size) {
    const int*   idx   = (const int*)  d_in[0];
    const float* tok   = (const float*)d_in[1];
    const float* pos   = (const float*)d_in[2];
    const float* Wq    = (const float*)d_in[3];
    const float* bq    = (const float*)d_in[4];
    const float* Wk    = (const float*)d_in[5];
    const float* bk    = (const float*)d_in[6];
    const float* Wv    = (const float*)d_in[7];
    const float* bv    = (const float*)d_in[8];
    const float* Wo    = (const float*)d_in[9];
    const float* bo    = (const float*)d_in[10];
    const float* W1    = (const float*)d_in[11];
    const float* b1    = (const float*)d_in[12];
    const float* W2    = (const float*)d_in[13];
    const float* b2    = (const float*)d_in[14];
    const float* ln1g  = (const float*)d_in[15];
    const float* ln1b  = (const float*)d_in[16];
    const float* ln2g  = (const float*)d_in[17];
    const float* ln2b  = (const float*)d_in[18];
    const float* lnfg  = (const float*)d_in[19];
    const float* lnfb  = (const float*)d_in[20];
    const float* Whead = (const float*)d_in[21];
    const float* bhead = (const float*)d_in[22];
    float* out = (float*)d_out;

    float *x, *q, *k, *v, *attn, *tmp, *ff, *scores;
    cudaGetSymbolAddress((void**)&x,      g_x);
    cudaGetSymbolAddress((void**)&q,      g_q);
    cudaGetSymbolAddress((void**)&k,      g_k);
    cudaGetSymbolAddress((void**)&v,      g_v);
    cudaGetSymbolAddress((void**)&attn,   g_attn);
    cudaGetSymbolAddress((void**)&tmp,    g_tmp);
    cudaGetSymbolAddress((void**)&ff,     g_ff);
    cudaGetSymbolAddress((void**)&scores, g_scores);

    embed_kernel<<<BT, 256>>>(idx, tok, pos, x);

    dim3 gEE(E_ / 128, BT / 128);      // N=1024
    dim3 gEF(FF_ / 128, BT / 128);     // N=4096
    dim3 gHead(V_ / 128, BT / 128);    // N=32000

    for (int l = 0; l < L_; l++) {
        const float* Wq_l = Wq + (size_t)l * E_ * E_;
        const float* Wk_l = Wk + (size_t)l * E_ * E_;
        const float* Wv_l = Wv + (size_t)l * E_ * E_;
        const float* Wo_l = Wo + (size_t)l * E_ * E_;
        const float* W1_l = W1 + (size_t)l * E_ * FF_;
        const float* W2_l = W2 + (size_t)l * FF_ * E_;
        const float* bq_l = bq + l * E_;
        const float* bk_l = bk + l * E_;
        const float* bv_l = bv + l * E_;
        const float* bo_l = bo + l * E_;
        const float* b1_l = b1 + l * FF_;
        const float* b2_l = b2 + l * E_;

        sgemm_kernel<false><<<gEE, 256>>>(x, Wq_l, bq_l, q, BT, E_, E_);
        sgemm_kernel<false><<<gEE, 256>>>(x, Wk_l, bk_l, k, BT, E_, E_);
        sgemm_kernel<false><<<gEE, 256>>>(x, Wv_l, bv_l, v, BT, E_, E_);

        attn_scores_kernel<<<dim3(16, 16, B_ * H_), 256>>>(q, k, scores);
        softmax_kernel<<<B_ * H_ * T_, 128>>>(scores);
        attn_av_kernel<<<dim3(16, B_ * H_), 256>>>(scores, v, attn);

        sgemm_kernel<false><<<gEE, 256>>>(attn, Wo_l, bo_l, tmp, BT, E_, E_);
        add_ln_kernel<<<BT, 256>>>(x, tmp, ln1g + l * E_, ln1b + l * E_, x);

        sgemm_kernel<true ><<<gEF, 256>>>(x, W1_l, b1_l, ff, BT, FF_, E_);
        sgemm_kernel<false><<<gEE, 256>>>(ff, W2_l, b2_l, tmp, BT, E_, FF_);
        add_ln_kernel<<<BT, 256>>>(x, tmp, ln2g + l * E_, ln2b + l * E_, x);
    }

    add_ln_kernel<<<BT, 256>>>(x, nullptr, lnfg, lnfb, x);
    sgemm_kernel<false><<<gHead, 256>>>(x, Whead, bhead, out, BT, V_, E_);
}

// round 3
// speedup vs baseline: 1.0021x; 1.0021x over previous
#include <cuda_runtime.h>
#include <math.h>
#include <stdint.h>

#define B_  4
#define T_  1024
#define E_  1024
#define H_  16
#define HD  64
#define L_  6
#define FF_ 4096
#define V_  32000
#define BT  (B_ * T_)

// ---------------- device scratch (static, no allocations) ----------------
__device__ float g_x[BT * E_];
__device__ float g_q[BT * E_];
__device__ float g_k[BT * E_];
__device__ float g_v[BT * E_];
__device__ float g_attn[BT * E_];
__device__ float g_tmp[BT * E_];
__device__ float g_ff[(size_t)BT * FF_];
__device__ float g_scores[(size_t)B_ * H_ * T_ * T_];   // 256 MiB

// ---------------- warp/block reductions ----------------
__device__ __forceinline__ float warpSum(float v) {
    #pragma unroll
    for (int o = 16; o > 0; o >>= 1) v += __shfl_xor_sync(0xffffffffu, v, o);
    return v;
}
__device__ __forceinline__ float warpMax(float v) {
    #pragma unroll
    for (int o = 16; o > 0; o >>= 1) v = fmaxf(v, __shfl_xor_sync(0xffffffffu, v, o));
    return v;
}

// ---------------- embedding: x[b,t,:] = tok[idx[b,t],:] + pos[t,:] ----------------
__global__ void embed_kernel(const int* __restrict__ idx,
                             const float* __restrict__ tok,
                             const float* __restrict__ pos,
                             float* __restrict__ x) {
    int bt = blockIdx.x;
    int t  = bt & (T_ - 1);
    int id = idx[bt];
    int c  = threadIdx.x;                 // 256 threads, float4 each = 1024 floats
    float4 a = ((const float4*)(tok + (size_t)id * E_))[c];
    float4 p = ((const float4*)(pos + (size_t)t  * E_))[c];
    a.x += p.x; a.y += p.y; a.z += p.z; a.w += p.w;
    ((float4*)(x + (size_t)bt * E_))[c] = a;
}

// ---------------- SGEMM: C = A(MxK) * B(KxN) + bias, optional ReLU ----------------
// Requires: M%128==0, N%128==0, K%16==0 (true for all shapes used here).
template<bool RELU>
__global__ __launch_bounds__(256, 2)
void sgemm_kernel(const float* __restrict__ A, const float* __restrict__ B,
                  const float* __restrict__ bias, float* __restrict__ C,
                  int M, int N, int K) {
    __shared__ float As[16][128];   // transposed: As[k][m]
    __shared__ float Bs[16][128];   // Bs[k][n]
    int tid = threadIdx.x;
    int tx = tid & 15, ty = tid >> 4;
    int bm = blockIdx.y * 128, bn = blockIdx.x * 128;

    const float* Ab = A + (size_t)bm * K;
    const float* Bb = B + bn;

    int arow = tid >> 2;            // 0..63
    int acol = (tid & 3) * 4;       // 0,4,8,12
    int brow = tid >> 5;            // 0..7
    int bcol = (tid & 31) * 4;      // 0..124

    float acc[8][8];
    #pragma unroll
    for (int i = 0; i < 8; i++)
        #pragma unroll
        for (int j = 0; j < 8; j++) acc[i][j] = 0.f;

    for (int k0 = 0; k0 < K; k0 += 16) {
        #pragma unroll
        for (int rr = 0; rr < 2; rr++) {
            float4 a = *(const float4*)(Ab + (size_t)(arow + rr * 64) * K + k0 + acol);
            As[acol + 0][arow + rr * 64] = a.x;
            As[acol + 1][arow + rr * 64] = a.y;
            As[acol + 2][arow + rr * 64] = a.z;
            As[acol + 3][arow + rr * 64] = a.w;
        }
        #pragma unroll
        for (int rr = 0; rr < 2; rr++) {
            float4 b4 = *(const float4*)(Bb + (size_t)(k0 + brow + rr * 8) * N + bcol);
            *(float4*)&Bs[brow + rr * 8][bcol] = b4;
        }
        __syncthreads();

        #pragma unroll
        for (int k = 0; k < 16; k++) {
            float ra[8], rb[8];
            *(float4*)&ra[0] = *(const float4*)&As[k][ty * 8];
            *(float4*)&ra[4] = *(const float4*)&As[k][ty * 8 + 4];
            *(float4*)&rb[0] = *(const float4*)&Bs[k][tx * 8];
            *(float4*)&rb[4] = *(const float4*)&Bs[k][tx * 8 + 4];
            #pragma unroll
            for (int i = 0; i < 8; i++)
                #pragma unroll
                for (int j = 0; j < 8; j++)
                    acc[i][j] = fmaf(ra[i], rb[j], acc[i][j]);
        }
        __syncthreads();
    }

    #pragma unroll
    for (int i = 0; i < 8; i++) {
        int row = bm + ty * 8 + i;
        #pragma unroll
        for (int j = 0; j < 8; j += 4) {
            int col = bn + tx * 8 + j;
            float4 v;
            v.x = acc[i][j]; v.y = acc[i][j + 1]; v.z = acc[i][j + 2]; v.w = acc[i][j + 3];
            v.x += bias[col]; v.y += bias[col + 1]; v.z += bias[col + 2]; v.w += bias[col + 3];
            if (RELU) {
                v.x = fmaxf(v.x, 0.f); v.y = fmaxf(v.y, 0.f);
                v.z = fmaxf(v.z, 0.f); v.w = fmaxf(v.w, 0.f);
            }
            *(float4*)(C + (size_t)row * N + col) = v;
        }
    }
}

// ---------------- attention scores: S[bh,i,j] = dot(Q,K)/8, causal ----------------
// grid (jt=16, it=16, bh=64), block 256. Only jt<=it tiles computed.
__global__ void attn_scores_kernel(const float* __restrict__ Q,
                                   const float* __restrict__ Kb,
                                   float* __restrict__ S) {
    int jt = blockIdx.x, it = blockIdx.y, bh = blockIdx.z;
    if (jt > it) return;
    int b = bh >> 4, h = bh & 15;

    __shared__ float Qs[64][65];
    __shared__ float Ks[64][65];
    int tid = threadIdx.x;
    #pragma unroll
    for (int p = 0; p < 4; p++) {
        int r = p * 16 + (tid >> 4);
        int c = (tid & 15) * 4;
        float4 qv = *(const float4*)(Q + ((size_t)(b * T_ + it * 64 + r) * E_) + h * HD + c);
        Qs[r][c] = qv.x; Qs[r][c + 1] = qv.y; Qs[r][c + 2] = qv.z; Qs[r][c + 3] = qv.w;
        float4 kv = *(const float4*)(Kb + ((size_t)(b * T_ + jt * 64 + r) * E_) + h * HD + c);
        Ks[r][c] = kv.x; Ks[r][c + 1] = kv.y; Ks[r][c + 2] = kv.z; Ks[r][c + 3] = kv.w;
    }
    __syncthreads();

    int tx = tid & 15, ty = tid >> 4;
    float acc[4][4] = {};
    #pragma unroll 8
    for (int d = 0; d < 64; d++) {
        float rq[4], rk[4];
        #pragma unroll
        for (int ii = 0; ii < 4; ii++) rq[ii] = Qs[ty * 4 + ii][d];
        #pragma unroll
        for (int jj = 0; jj < 4; jj++) rk[jj] = Ks[tx * 4 + jj][d];
        #pragma unroll
        for (int ii = 0; ii < 4; ii++)
            #pragma unroll
            for (int jj = 0; jj < 4; jj++)
                acc[ii][jj] = fmaf(rq[ii], rk[jj], acc[ii][jj]);
    }

    #pragma unroll
    for (int ii = 0; ii < 4; ii++) {
        int ig = it * 64 + ty * 4 + ii;
        #pragma unroll
        for (int jj = 0; jj < 4; jj++) {
            int jg = jt * 64 + tx * 4 + jj;
            float v = acc[ii][jj] * 0.125f;          // 1/sqrt(64)
            if (jg > ig) v = -1e30f;
            S[((size_t)bh * T_ + ig) * T_ + jg] = v;
        }
    }
}

// ---------------- row softmax over j <= i (in place) ----------------
__global__ void softmax_kernel(float* __restrict__ S) {
    int rid = blockIdx.x;
    int bh = rid >> 10, i = rid & 1023;
    float* row = S + ((size_t)bh * T_ + i) * T_;
    int n = i + 1;
    int t = threadIdx.x;                   // 128 threads

    float vals[8];
    float m = -1e30f;
    #pragma unroll
    for (int k = 0; k < 8; k++) {
        int j = t + k * 128;
        vals[k] = (j < n) ? row[j] : -1e30f;
        m = fmaxf(m, vals[k]);
    }
    __shared__ float sh[8];
    m = warpMax(m);
    int w = t >> 5, lane = t & 31;
    if (lane == 0) sh[w] = m;
    __syncthreads();
    if (w == 0) {
        float a = (lane < 4) ? sh[lane] : -1e30f;
        a = warpMax(a);
        if (lane == 0) sh[0] = a;
    }
    __syncthreads();
    float M = sh[0];

    float s = 0.f;
    #pragma unroll
    for (int k = 0; k < 8; k++) {
        int j = t + k * 128;
        if (j < n) { vals[k] = expf(vals[k] - M); s += vals[k]; }
    }
    __syncthreads();
    s = warpSum(s);
    if (lane == 0) sh[w] = s;
    __syncthreads();
    if (w == 0) {
        float a = (lane < 4) ? sh[lane] : 0.f;
        a = warpSum(a);
        if (lane == 0) sh[0] = a;
    }
    __syncthreads();
    float inv = 1.f / sh[0];

    #pragma unroll
    for (int k = 0; k < 8; k++) {
        int j = t + k * 128;
        if (j < n) row[j] = vals[k] * inv;
    }
}

// ---------------- O[b,i,h,:] = sum_j P[bh,i,j] V[b,j,h,:] ----------------
// grid (it=16, bh=64), block 256; loops jt = 0..it (triangular).
__global__ void attn_av_kernel(const float* __restrict__ S,
                               const float* __restrict__ Vb,
                               float* __restrict__ O) {
    int it = blockIdx.x, bh = blockIdx.y;
    int b = bh >> 4, h = bh & 15;
    __shared__ float Ps[64][65];
    __shared__ float Vs[64][65];
    int tid = threadIdx.x;
    int tx = tid & 15, ty = tid >> 4;
    float acc[4][4] = {};

    for (int jt = 0; jt <= it; jt++) {
        #pragma unroll
        for (int p = 0; p < 4; p++) {
            int r = p * 16 + (tid >> 4);
            int c = (tid & 15) * 4;
            int ig = it * 64 + r;
            int jg = jt * 64 + c;
            float4 s4 = *(const float4*)(S + ((size_t)bh * T_ + ig) * T_ + jg);
            Ps[r][c + 0] = (jg + 0 <= ig) ? s4.x : 0.f;
            Ps[r][c + 1] = (jg + 1 <= ig) ? s4.y : 0.f;
            Ps[r][c + 2] = (jg + 2 <= ig) ? s4.z : 0.f;
            Ps[r][c + 3] = (jg + 3 <= ig) ? s4.w : 0.f;
            float4 vv = *(const float4*)(Vb + ((size_t)(b * T_ + jt * 64 + r) * E_) + h * HD + c);
            Vs[r][c] = vv.x; Vs[r][c + 1] = vv.y; Vs[r][c + 2] = vv.z; Vs[r][c + 3] = vv.w;
        }
        __syncthreads();
        #pragma unroll 8
        for (int j = 0; j < 64; j++) {
            float rp[4], rv[4];
            #pragma unroll
            for (int ii = 0; ii < 4; ii++) rp[ii] = Ps[ty * 4 + ii][j];
            #pragma unroll
            for (int jj = 0; jj < 4; jj++) rv[jj] = Vs[j][tx * 4 + jj];
            #pragma unroll
            for (int ii = 0; ii < 4; ii++)
                #pragma unroll
                for (int jj = 0; jj < 4; jj++)
                    acc[ii][jj] = fmaf(rp[ii], rv[jj], acc[ii][jj]);
        }
        __syncthreads();
    }

    #pragma unroll
    for (int ii = 0; ii < 4; ii++) {
        int ig = it * 64 + ty * 4 + ii;
        #pragma unroll
        for (int jj = 0; jj < 4; jj++)
            O[((size_t)(b * T_ + ig)) * E_ + h * HD + tx * 4 + jj] = acc[ii][jj];
    }
}

// ---------------- out = LayerNorm(in (+ res)) * g + b ----------------
__global__ void add_ln_kernel(const float* __restrict__ in,
                              const float* __restrict__ res,    // nullable
                              const float* __restrict__ g,
                              const float* __restrict__ bb,
                              float* __restrict__ out) {
    int row = blockIdx.x;
    int t = threadIdx.x;                        // 256 threads * float4 = 1024
    float4 v = ((const float4*)(in + (size_t)row * E_))[t];
    if (res) {
        float4 r = ((const float4*)(res + (size_t)row * E_))[t];
        v.x += r.x; v.y += r.y; v.z += r.z; v.w += r.w;
    }
    float s  = v.x + v.y + v.z + v.w;
    float s2 = v.x * v.x + v.y * v.y + v.z * v.z + v.w * v.w;

    __shared__ float sh[16];
    s = warpSum(s); s2 = warpSum(s2);
    int w = t >> 5, lane = t & 31;
    if (lane == 0) { sh[w] = s; sh[w + 8] = s2; }
    __syncthreads();
    if (w == 0) {
        float a  = (lane < 8) ? sh[lane] : 0.f;
        a = warpSum(a);
        float a2 = (lane < 8) ? sh[lane + 8] : 0.f;
        a2 = warpSum(a2);
        if (lane == 0) { sh[0] = a; sh[8] = a2; }
    }
    __syncthreads();
    float mean = sh[0] * (1.f / E_);
    float var  = sh[8] * (1.f / E_) - mean * mean;
    float rstd = rsqrtf(var + 1e-5f);

    float4 gv = ((const float4*)g)[t];
    float4 bv = ((const float4*)bb)[t];
    float4 o;
    o.x = (v.x - mean) * rstd * gv.x + bv.x;
    o.y = (v.y - mean) * rstd * gv.y + bv.y;
    o.z = (v.z - mean) * rstd * gv.z + bv.z;
    o.w = (v.w - mean) * rstd * gv.w + bv.w;
    ((float4*)(out + (size_t)row * E_))[t] = o;
}

// ---------------- host launch ----------------
extern "C" void kernel_launch(void* const* d_in, const int* in_sizes, int n_in,
                              void* d_out, int out_size) {
    const int*   idx   = (const int*)  d_in[0];
    const float* tok   = (const float*)d_in[1];
    const float* pos   = (const float*)d_in[2];
    const float* Wq    = (const float*)d_in[3];
    const float* bq    = (const float*)d_in[4];
    const float* Wk    = (const float*)d_in[5];
    const float* bk    = (const float*)d_in[6];
    const float* Wv    = (const float*)d_in[7];
    const float* bv    = (const float*)d_in[8];
    const float* Wo    = (const float*)d_in[9];
    const float* bo    = (const float*)d_in[10];
    const float* W1    = (const float*)d_in[11];
    const float* b1    = (const float*)d_in[12];
    const float* W2    = (const float*)d_in[13];
    const float* b2    = (const float*)d_in[14];
    const float* ln1g  = (const float*)d_in[15];
    const float* ln1b  = (const float*)d_in[16];
    const float* ln2g  = (const float*)d_in[17];
    const float* ln2b  = (const float*)d_in[18];
    const float* lnfg  = (const float*)d_in[19];
    const float* lnfb  = (const float*)d_in[20];
    const float* Whead = (const float*)d_in[21];
    const float* bhead = (const float*)d_in[22];
    float* out = (float*)d_out;

    float *x, *q, *k, *v, *attn, *tmp, *ff, *scores;
    cudaGetSymbolAddress((void**)&x,      g_x);
    cudaGetSymbolAddress((void**)&q,      g_q);
    cudaGetSymbolAddress((void**)&k,      g_k);
    cudaGetSymbolAddress((void**)&v,      g_v);
    cudaGetSymbolAddress((void**)&attn,   g_attn);
    cudaGetSymbolAddress((void**)&tmp,    g_tmp);
    cudaGetSymbolAddress((void**)&ff,     g_ff);
    cudaGetSymbolAddress((void**)&scores, g_scores);

    embed_kernel<<<BT, 256>>>(idx, tok, pos, x);

    dim3 gEE(E_ / 128, BT / 128);      // N=1024
    dim3 gEF(FF_ / 128, BT / 128);     // N=4096
    dim3 gHead(V_ / 128, BT / 128);    // N=32000

    for (int l = 0; l < L_; l++) {
        const float* Wq_l = Wq + (size_t)l * E_ * E_;
        const float* Wk_l = Wk + (size_t)l * E_ * E_;
        const float* Wv_l = Wv + (size_t)l * E_ * E_;
        const float* Wo_l = Wo + (size_t)l * E_ * E_;
        const float* W1_l = W1 + (size_t)l * E_ * FF_;
        const float* W2_l = W2 + (size_t)l * FF_ * E_;
        const float* bq_l = bq + l * E_;
        const float* bk_l = bk + l * E_;
        const float* bv_l = bv + l * E_;
        const float* bo_l = bo + l * E_;
        const float* b1_l = b1 + l * FF_;
        const float* b2_l = b2 + l * E_;

        sgemm_kernel<false><<<gEE, 256>>>(x, Wq_l, bq_l, q, BT, E_, E_);
        sgemm_kernel<false><<<gEE, 256>>>(x, Wk_l, bk_l, k, BT, E_, E_);
        sgemm_kernel<false><<<gEE, 256>>>(x, Wv_l, bv_l, v, BT, E_, E_);

        attn_scores_kernel<<<dim3(16, 16, B_ * H_), 256>>>(q, k, scores);
        softmax_kernel<<<B_ * H_ * T_, 128>>>(scores);
        attn_av_kernel<<<dim3(16, B_ * H_), 256>>>(scores, v, attn);

        sgemm_kernel<false><<<gEE, 256>>>(attn, Wo_l, bo_l, tmp, BT, E_, E_);
        add_ln_kernel<<<BT, 256>>>(x, tmp, ln1g + l * E_, ln1b + l * E_, x);

        sgemm_kernel<true ><<<gEF, 256>>>(x, W1_l, b1_l, ff, BT, FF_, E_);
        sgemm_kernel<false><<<gEE, 256>>>(ff, W2_l, b2_l, tmp, BT, E_, FF_);
        add_ln_kernel<<<BT, 256>>>(x, tmp, ln2g + l * E_, ln2b + l * E_, x);
    }

    add_ln_kernel<<<BT, 256>>>(x, nullptr, lnfg, lnfb, x);
    sgemm_kernel<false><<<gHead, 256>>>(x, Whead, bhead, out, BT, V_, E_);
}

// round 4
// speedup vs baseline: 1.5578x; 1.5545x over previous
#include <cuda_runtime.h>
#include <cuda_bf16.h>
#include <math.h>
#include <stdint.h>

#define B_  4
#define T_  1024
#define E_  1024
#define H_  16
#define HD  64
#define L_  6
#define FF_ 4096
#define V_  32000
#define BT  (B_ * T_)

#define SZ_EE (E_ * E_)
// transposed-weight element offsets (bf16 planes)
#define OWQ   ((size_t)0)
#define OWK   ((size_t)6 * SZ_EE)
#define OWV   ((size_t)12 * SZ_EE)
#define OWO   ((size_t)18 * SZ_EE)
#define OW1   ((size_t)24 * SZ_EE)
#define OW2   ((size_t)48 * SZ_EE)
#define OHEAD ((size_t)72 * SZ_EE)
#define WTOT  (OHEAD + (size_t)E_ * V_)

// ---------------- device scratch (static, no allocations) ----------------
__device__ float g_x[BT * E_];
__device__ float g_q[BT * E_];
__device__ float g_k[BT * E_];
__device__ float g_v[BT * E_];
__device__ float g_attn[BT * E_];
__device__ float g_tmp[BT * E_];
__device__ float g_ff[(size_t)BT * FF_];
__device__ float g_scores[(size_t)B_ * H_ * T_ * T_];   // 256 MiB
__device__ __nv_bfloat16 g_wth[WTOT];                   // weights^T hi
__device__ __nv_bfloat16 g_wtl[WTOT];                   // weights^T lo
__device__ __nv_bfloat16 g_ah[(size_t)BT * FF_];        // activation hi
__device__ __nv_bfloat16 g_al[(size_t)BT * FF_];        // activation lo

// ---------------- helpers ----------------
__device__ __forceinline__ float warpSum(float v) {
    #pragma unroll
    for (int o = 16; o > 0; o >>= 1) v += __shfl_xor_sync(0xffffffffu, v, o);
    return v;
}
__device__ __forceinline__ float warpMax(float v) {
    #pragma unroll
    for (int o = 16; o > 0; o >>= 1) v = fmaxf(v, __shfl_xor_sync(0xffffffffu, v, o));
    return v;
}
__device__ __forceinline__ void bsplit(float x, __nv_bfloat16& h, __nv_bfloat16& l) {
    h = __float2bfloat16(x);
    l = __float2bfloat16(x - __bfloat162float(h));
}
__device__ __forceinline__ unsigned pack2(__nv_bfloat16 a, __nv_bfloat16 b) {
    return (unsigned)__bfloat16_as_ushort(a) | ((unsigned)__bfloat16_as_ushort(b) << 16);
}

// ---------------- embedding ----------------
__global__ void embed_kernel(const int* __restrict__ idx,
                             const float* __restrict__ tok,
                             const float* __restrict__ pos,
                             float* __restrict__ x) {
    int bt = blockIdx.x;
    int t  = bt & (T_ - 1);
    int id = idx[bt];
    int c  = threadIdx.x;
    float4 a = ((const float4*)(tok + (size_t)id * E_))[c];
    float4 p = ((const float4*)(pos + (size_t)t  * E_))[c];
    a.x += p.x; a.y += p.y; a.z += p.z; a.w += p.w;
    ((float4*)(x + (size_t)bt * E_))[c] = a;
}

// ---------------- weight transpose + bf16 hi/lo split ----------------
// W: [K,N] f32 (per layer, layer = blockIdx.z) -> Th/Tl: [N,K] bf16
__global__ void tconv_kernel(const float* __restrict__ W,
                             __nv_bfloat16* __restrict__ Th,
                             __nv_bfloat16* __restrict__ Tl,
                             int K, int N) {
    __shared__ float tile[32][33];
    size_t loff = (size_t)blockIdx.z * K * N;
    const float* Wl = W + loff;
    __nv_bfloat16* Thl = Th + loff;
    __nv_bfloat16* Tll = Tl + loff;
    int n0 = blockIdx.x * 32, k0 = blockIdx.y * 32;
    int tx = threadIdx.x & 31, ty = threadIdx.x >> 5;   // 32x8
    #pragma unroll
    for (int i = 0; i < 4; i++)
        tile[ty + i * 8][tx] = Wl[(size_t)(k0 + ty + i * 8) * N + n0 + tx];
    __syncthreads();
    #pragma unroll
    for (int i = 0; i < 4; i++) {
        int n = n0 + ty + i * 8;
        int k = k0 + tx;
        __nv_bfloat16 h, l;
        bsplit(tile[tx][ty + i * 8], h, l);
        Thl[(size_t)n * K + k] = h;
        Tll[(size_t)n * K + k] = l;
    }
}

// ---------------- activation bf16 hi/lo split (elementwise) ----------------
__global__ void conv_act_kernel(const float* __restrict__ in,
                                __nv_bfloat16* __restrict__ h,
                                __nv_bfloat16* __restrict__ l) {
    size_t i = (size_t)blockIdx.x * 256 + threadIdx.x;
    float4 v = ((const float4*)in)[i];
    __nv_bfloat16 h0, h1, h2, h3, l0, l1, l2, l3;
    bsplit(v.x, h0, l0); bsplit(v.y, h1, l1);
    bsplit(v.z, h2, l2); bsplit(v.w, h3, l3);
    uint2 hh, ll;
    hh.x = pack2(h0, h1); hh.y = pack2(h2, h3);
    ll.x = pack2(l0, l1); ll.y = pack2(l2, l3);
    ((uint2*)h)[i] = hh;
    ((uint2*)l)[i] = ll;
}

// ---------------- tensor-core GEMM: C = A * W + bias (opt ReLU) ----------------
// A: hi/lo bf16 [M,K] (K contiguous). B: hi/lo bf16 [N,K] (K contiguous, i.e. W^T).
// 3-pass bf16 split: ah*bh + ah*bl + al*bh. CTA tile 128x128, k-chunk 32.
__device__ __forceinline__ void mma16816(float* c, const uint32_t* a, const uint32_t* b) {
    asm volatile(
        "mma.sync.aligned.m16n8k16.row.col.f32.bf16.bf16.f32 "
        "{%0,%1,%2,%3}, {%4,%5,%6,%7}, {%8,%9}, {%0,%1,%2,%3};\n"
        : "+f"(c[0]), "+f"(c[1]), "+f"(c[2]), "+f"(c[3])
        : "r"(a[0]), "r"(a[1]), "r"(a[2]), "r"(a[3]), "r"(b[0]), "r"(b[1]));
}

__global__ __launch_bounds__(256, 1)
void mma_gemm_kernel(const __nv_bfloat16* __restrict__ Ah, const __nv_bfloat16* __restrict__ Al,
                     const __nv_bfloat16* __restrict__ Bh, const __nv_bfloat16* __restrict__ Bl,
                     const float* __restrict__ bias, float* __restrict__ C,
                     int M, int N, int K, int relu) {
    // row pitch 72 bf16 (144B): hi at k in [0,32), lo at [40,72).
    // fragment bank index = 4*g + tq  (bijective within warp -> conflict-free)
    __shared__ __align__(16) __nv_bfloat16 As[128][72];
    __shared__ __align__(16) __nv_bfloat16 Bs[128][72];

    int tid  = threadIdx.x;
    int wid  = tid >> 5, lane = tid & 31;
    int g    = lane >> 2, tq = lane & 3;
    int wm   = (wid >> 2) * 64;      // warp grid 2 (m) x 4 (n)
    int wn   = (wid & 3) * 32;
    int bm   = blockIdx.y * 128, bn = blockIdx.x * 128;

    const __nv_bfloat16* Aho = Ah + (size_t)bm * K;
    const __nv_bfloat16* Alo = Al + (size_t)bm * K;
    const __nv_bfloat16* Bho = Bh + (size_t)bn * K;
    const __nv_bfloat16* Blo = Bl + (size_t)bn * K;

    float acc[4][4][4];
    #pragma unroll
    for (int a = 0; a < 4; a++)
        #pragma unroll
        for (int b = 0; b < 4; b++)
            #pragma unroll
            for (int c = 0; c < 4; c++) acc[a][b][c] = 0.f;

    for (int k0 = 0; k0 < K; k0 += 32) {
        #pragma unroll
        for (int i = 0; i < 2; i++) {
            int idx = tid + i * 256;          // 0..511
            int row = idx >> 2;
            int kq  = (idx & 3) << 3;         // 0,8,16,24
            *(float4*)&As[row][kq]      = *(const float4*)(Aho + (size_t)row * K + k0 + kq);
            *(float4*)&As[row][40 + kq] = *(const float4*)(Alo + (size_t)row * K + k0 + kq);
            *(float4*)&Bs[row][kq]      = *(const float4*)(Bho + (size_t)row * K + k0 + kq);
            *(float4*)&Bs[row][40 + kq] = *(const float4*)(Blo + (size_t)row * K + k0 + kq);
        }
        __syncthreads();

        #pragma unroll
        for (int kk = 0; kk < 32; kk += 16) {
            uint32_t ah[4][4], al[4][4], bh[4][2], bl[4][2];
            #pragma unroll
            for (int mi = 0; mi < 4; mi++) {
                int r = wm + mi * 16 + g;
                int kc = kk + 2 * tq;
                ah[mi][0] = *(const uint32_t*)&As[r][kc];
                ah[mi][1] = *(const uint32_t*)&As[r + 8][kc];
                ah[mi][2] = *(const uint32_t*)&As[r][kc + 8];
                ah[mi][3] = *(const uint32_t*)&As[r + 8][kc + 8];
                al[mi][0] = *(const uint32_t*)&As[r][40 + kc];
                al[mi][1] = *(const uint32_t*)&As[r + 8][40 + kc];
                al[mi][2] = *(const uint32_t*)&As[r][40 + kc + 8];
                al[mi][3] = *(const uint32_t*)&As[r + 8][40 + kc + 8];
            }
            #pragma unroll
            for (int ni = 0; ni < 4; ni++) {
                int rj = wn + ni * 8 + g;
                int kc = kk + 2 * tq;
                bh[ni][0] = *(const uint32_t*)&Bs[rj][kc];
                bh[ni][1] = *(const uint32_t*)&Bs[rj][kc + 8];
                bl[ni][0] = *(const uint32_t*)&Bs[rj][40 + kc];
                bl[ni][1] = *(const uint32_t*)&Bs[rj][40 + kc + 8];
            }
            #pragma unroll
            for (int mi = 0; mi < 4; mi++)
                #pragma unroll
                for (int ni = 0; ni < 4; ni++) {
                    mma16816(acc[mi][ni], ah[mi], bh[ni]);
                    mma16816(acc[mi][ni], ah[mi], bl[ni]);
                    mma16816(acc[mi][ni], al[mi], bh[ni]);
                }
        }
        __syncthreads();
    }

    #pragma unroll
    for (int mi = 0; mi < 4; mi++) {
        int r0 = bm + wm + mi * 16 + g;
        #pragma unroll
        for (int ni = 0; ni < 4; ni++) {
            int c0 = bn + wn + ni * 8 + 2 * tq;
            float bx = bias[c0], by = bias[c0 + 1];
            float2 v0, v1;
            v0.x = acc[mi][ni][0] + bx; v0.y = acc[mi][ni][1] + by;
            v1.x = acc[mi][ni][2] + bx; v1.y = acc[mi][ni][3] + by;
            if (relu) {
                v0.x = fmaxf(v0.x, 0.f); v0.y = fmaxf(v0.y, 0.f);
                v1.x = fmaxf(v1.x, 0.f); v1.y = fmaxf(v1.y, 0.f);
            }
            *(float2*)(C + (size_t)r0 * N + c0)       = v0;
            *(float2*)(C + (size_t)(r0 + 8) * N + c0) = v1;
        }
    }
}

// ---------------- attention scores: S[bh,i,j] = dot(Q,K)/8, causal ----------------
__global__ void attn_scores_kernel(const float* __restrict__ Q,
                                   const float* __restrict__ Kb,
                                   float* __restrict__ S) {
    int jt = blockIdx.x, it = blockIdx.y, bh = blockIdx.z;
    if (jt > it) return;
    int b = bh >> 4, h = bh & 15;

    __shared__ float Qs[64][65];
    __shared__ float Ks[64][65];
    int tid = threadIdx.x;
    #pragma unroll
    for (int p = 0; p < 4; p++) {
        int r = p * 16 + (tid >> 4);
        int c = (tid & 15) * 4;
        float4 qv = *(const float4*)(Q + ((size_t)(b * T_ + it * 64 + r) * E_) + h * HD + c);
        Qs[r][c] = qv.x; Qs[r][c + 1] = qv.y; Qs[r][c + 2] = qv.z; Qs[r][c + 3] = qv.w;
        float4 kv = *(const float4*)(Kb + ((size_t)(b * T_ + jt * 64 + r) * E_) + h * HD + c);
        Ks[r][c] = kv.x; Ks[r][c + 1] = kv.y; Ks[r][c + 2] = kv.z; Ks[r][c + 3] = kv.w;
    }
    __syncthreads();

    int tx = tid & 15, ty = tid >> 4;
    float acc[4][4] = {};
    #pragma unroll 8
    for (int d = 0; d < 64; d++) {
        float rq[4], rk[4];
        #pragma unroll
        for (int ii = 0; ii < 4; ii++) rq[ii] = Qs[ty * 4 + ii][d];
        #pragma unroll
        for (int jj = 0; jj < 4; jj++) rk[jj] = Ks[tx * 4 + jj][d];
        #pragma unroll
        for (int ii = 0; ii < 4; ii++)
            #pragma unroll
            for (int jj = 0; jj < 4; jj++)
                acc[ii][jj] = fmaf(rq[ii], rk[jj], acc[ii][jj]);
    }

    #pragma unroll
    for (int ii = 0; ii < 4; ii++) {
        int ig = it * 64 + ty * 4 + ii;
        #pragma unroll
        for (int jj = 0; jj < 4; jj++) {
            int jg = jt * 64 + tx * 4 + jj;
            float v = acc[ii][jj] * 0.125f;
            if (jg > ig) v = -1e30f;
            S[((size_t)bh * T_ + ig) * T_ + jg] = v;
        }
    }
}

// ---------------- row softmax over j <= i (in place) ----------------
__global__ void softmax_kernel(float* __restrict__ S) {
    int rid = blockIdx.x;
    int bh = rid >> 10, i = rid & 1023;
    float* row = S + ((size_t)bh * T_ + i) * T_;
    int n = i + 1;
    int t = threadIdx.x;

    float vals[8];
    float m = -1e30f;
    #pragma unroll
    for (int k = 0; k < 8; k++) {
        int j = t + k * 128;
        vals[k] = (j < n) ? row[j] : -1e30f;
        m = fmaxf(m, vals[k]);
    }
    __shared__ float sh[8];
    m = warpMax(m);
    int w = t >> 5, lane = t & 31;
    if (lane == 0) sh[w] = m;
    __syncthreads();
    if (w == 0) {
        float a = (lane < 4) ? sh[lane] : -1e30f;
        a = warpMax(a);
        if (lane == 0) sh[0] = a;
    }
    __syncthreads();
    float M = sh[0];

    float s = 0.f;
    #pragma unroll
    for (int k = 0; k < 8; k++) {
        int j = t + k * 128;
        if (j < n) { vals[k] = expf(vals[k] - M); s += vals[k]; }
    }
    __syncthreads();
    s = warpSum(s);
    if (lane == 0) sh[w] = s;
    __syncthreads();
    if (w == 0) {
        float a = (lane < 4) ? sh[lane] : 0.f;
        a = warpSum(a);
        if (lane == 0) sh[0] = a;
    }
    __syncthreads();
    float inv = 1.f / sh[0];

    #pragma unroll
    for (int k = 0; k < 8; k++) {
        int j = t + k * 128;
        if (j < n) row[j] = vals[k] * inv;
    }
}

// ---------------- O = P * V ----------------
__global__ void attn_av_kernel(const float* __restrict__ S,
                               const float* __restrict__ Vb,
                               float* __restrict__ O) {
    int it = blockIdx.x, bh = blockIdx.y;
    int b = bh >> 4, h = bh & 15;
    __shared__ float Ps[64][65];
    __shared__ float Vs[64][65];
    int tid = threadIdx.x;
    int tx = tid & 15, ty = tid >> 4;
    float acc[4][4] = {};

    for (int jt = 0; jt <= it; jt++) {
        #pragma unroll
        for (int p = 0; p < 4; p++) {
            int r = p * 16 + (tid >> 4);
            int c = (tid & 15) * 4;
            int ig = it * 64 + r;
            int jg = jt * 64 + c;
            float4 s4 = *(const float4*)(S + ((size_t)bh * T_ + ig) * T_ + jg);
            Ps[r][c + 0] = (jg + 0 <= ig) ? s4.x : 0.f;
            Ps[r][c + 1] = (jg + 1 <= ig) ? s4.y : 0.f;
            Ps[r][c + 2] = (jg + 2 <= ig) ? s4.z : 0.f;
            Ps[r][c + 3] = (jg + 3 <= ig) ? s4.w : 0.f;
            float4 vv = *(const float4*)(Vb + ((size_t)(b * T_ + jt * 64 + r) * E_) + h * HD + c);
            Vs[r][c] = vv.x; Vs[r][c + 1] = vv.y; Vs[r][c + 2] = vv.z; Vs[r][c + 3] = vv.w;
        }
        __syncthreads();
        #pragma unroll 8
        for (int j = 0; j < 64; j++) {
            float rp[4], rv[4];
            #pragma unroll
            for (int ii = 0; ii < 4; ii++) rp[ii] = Ps[ty * 4 + ii][j];
            #pragma unroll
            for (int jj = 0; jj < 4; jj++) rv[jj] = Vs[j][tx * 4 + jj];
            #pragma unroll
            for (int ii = 0; ii < 4; ii++)
                #pragma unroll
                for (int jj = 0; jj < 4; jj++)
                    acc[ii][jj] = fmaf(rp[ii], rv[jj], acc[ii][jj]);
        }
        __syncthreads();
    }

    #pragma unroll
    for (int ii = 0; ii < 4; ii++) {
        int ig = it * 64 + ty * 4 + ii;
        #pragma unroll
        for (int jj = 0; jj < 4; jj++)
            O[((size_t)(b * T_ + ig)) * E_ + h * HD + tx * 4 + jj] = acc[ii][jj];
    }
}

// ---------------- out = LayerNorm(in (+ res)) * g + b ----------------
__global__ void add_ln_kernel(const float* __restrict__ in,
                              const float* __restrict__ res,
                              const float* __restrict__ g,
                              const float* __restrict__ bb,
                              float* __restrict__ out) {
    int row = blockIdx.x;
    int t = threadIdx.x;
    float4 v = ((const float4*)(in + (size_t)row * E_))[t];
    if (res) {
        float4 r = ((const float4*)(res + (size_t)row * E_))[t];
        v.x += r.x; v.y += r.y; v.z += r.z; v.w += r.w;
    }
    float s  = v.x + v.y + v.z + v.w;
    float s2 = v.x * v.x + v.y * v.y + v.z * v.z + v.w * v.w;

    __shared__ float sh[16];
    s = warpSum(s); s2 = warpSum(s2);
    int w = t >> 5, lane = t & 31;
    if (lane == 0) { sh[w] = s; sh[w + 8] = s2; }
    __syncthreads();
    if (w == 0) {
        float a  = (lane < 8) ? sh[lane] : 0.f;
        a = warpSum(a);
        float a2 = (lane < 8) ? sh[lane + 8] : 0.f;
        a2 = warpSum(a2);
        if (lane == 0) { sh[0] = a; sh[8] = a2; }
    }
    __syncthreads();
    float mean = sh[0] * (1.f / E_);
    float var  = sh[8] * (1.f / E_) - mean * mean;
    float rstd = rsqrtf(var + 1e-5f);

    float4 gv = ((const float4*)g)[t];
    float4 bv = ((const float4*)bb)[t];
    float4 o;
    o.x = (v.x - mean) * rstd * gv.x + bv.x;
    o.y = (v.y - mean) * rstd * gv.y + bv.y;
    o.z = (v.z - mean) * rstd * gv.z + bv.z;
    o.w = (v.w - mean) * rstd * gv.w + bv.w;
    ((float4*)(out + (size_t)row * E_))[t] = o;
}

// ---------------- host launch ----------------
extern "C" void kernel_launch(void* const* d_in, const int* in_sizes, int n_in,
                              void* d_out, int out_size) {
    const int*   idx   = (const int*)  d_in[0];
    const float* tok   = (const float*)d_in[1];
    const float* pos   = (const float*)d_in[2];
    const float* Wq    = (const float*)d_in[3];
    const float* bq    = (const float*)d_in[4];
    const float* Wk    = (const float*)d_in[5];
    const float* bk    = (const float*)d_in[6];
    const float* Wv    = (const float*)d_in[7];
    const float* bv    = (const float*)d_in[8];
    const float* Wo    = (const float*)d_in[9];
    const float* bo    = (const float*)d_in[10];
    const float* W1    = (const float*)d_in[11];
    const float* b1    = (const float*)d_in[12];
    const float* W2    = (const float*)d_in[13];
    const float* b2    = (const float*)d_in[14];
    const float* ln1g  = (const float*)d_in[15];
    const float* ln1b  = (const float*)d_in[16];
    const float* ln2g  = (const float*)d_in[17];
    const float* ln2b  = (const float*)d_in[18];
    const float* lnfg  = (const float*)d_in[19];
    const float* lnfb  = (const float*)d_in[20];
    const float* Whead = (const float*)d_in[21];
    const float* bhead = (const float*)d_in[22];
    float* out = (float*)d_out;

    float *x, *q, *k, *v, *attn, *tmp, *ff, *scores;
    __nv_bfloat16 *wth, *wtl, *ah, *al;
    cudaGetSymbolAddress((void**)&x,      g_x);
    cudaGetSymbolAddress((void**)&q,      g_q);
    cudaGetSymbolAddress((void**)&k,      g_k);
    cudaGetSymbolAddress((void**)&v,      g_v);
    cudaGetSymbolAddress((void**)&attn,   g_attn);
    cudaGetSymbolAddress((void**)&tmp,    g_tmp);
    cudaGetSymbolAddress((void**)&ff,     g_ff);
    cudaGetSymbolAddress((void**)&scores, g_scores);
    cudaGetSymbolAddress((void**)&wth,    g_wth);
    cudaGetSymbolAddress((void**)&wtl,    g_wtl);
    cudaGetSymbolAddress((void**)&ah,     g_ah);
    cudaGetSymbolAddress((void**)&al,     g_al);

    // --- weight transpose + split (replayed each iteration; ~150us) ---
    tconv_kernel<<<dim3(E_ / 32,  E_ / 32,  L_), 256>>>(Wq,    wth + OWQ,   wtl + OWQ,   E_,  E_);
    tconv_kernel<<<dim3(E_ / 32,  E_ / 32,  L_), 256>>>(Wk,    wth + OWK,   wtl + OWK,   E_,  E_);
    tconv_kernel<<<dim3(E_ / 32,  E_ / 32,  L_), 256>>>(Wv,    wth + OWV,   wtl + OWV,   E_,  E_);
    tconv_kernel<<<dim3(E_ / 32,  E_ / 32,  L_), 256>>>(Wo,    wth + OWO,   wtl + OWO,   E_,  E_);
    tconv_kernel<<<dim3(FF_ / 32, E_ / 32,  L_), 256>>>(W1,    wth + OW1,   wtl + OW1,   E_,  FF_);
    tconv_kernel<<<dim3(E_ / 32,  FF_ / 32, L_), 256>>>(W2,    wth + OW2,   wtl + OW2,   FF_, E_);
    tconv_kernel<<<dim3(V_ / 32,  E_ / 32,  1 ), 256>>>(Whead, wth + OHEAD, wtl + OHEAD, E_,  V_);

    embed_kernel<<<BT, 256>>>(idx, tok, pos, x);

    dim3 gEE(E_ / 128, BT / 128);
    dim3 gEF(FF_ / 128, BT / 128);
    dim3 gHead(V_ / 128, BT / 128);
    int cE  = BT * E_ / 1024;     // conv_act grid for E-wide activations
    int cFF = BT * FF_ / 1024;

    for (int l = 0; l < L_; l++) {
        const float* bq_l = bq + l * E_;
        const float* bk_l = bk + l * E_;
        const float* bv_l = bv + l * E_;
        const float* bo_l = bo + l * E_;
        const float* b1_l = b1 + l * FF_;
        const float* b2_l = b2 + l * E_;

        conv_act_kernel<<<cE, 256>>>(x, ah, al);
        mma_gemm_kernel<<<gEE, 256>>>(ah, al, wth + OWQ + (size_t)l * SZ_EE, wtl + OWQ + (size_t)l * SZ_EE,
                                      bq_l, q, BT, E_, E_, 0);
        mma_gemm_kernel<<<gEE, 256>>>(ah, al, wth + OWK + (size_t)l * SZ_EE, wtl + OWK + (size_t)l * SZ_EE,
                                      bk_l, k, BT, E_, E_, 0);
        mma_gemm_kernel<<<gEE, 256>>>(ah, al, wth + OWV + (size_t)l * SZ_EE, wtl + OWV + (size_t)l * SZ_EE,
                                      bv_l, v, BT, E_, E_, 0);

        attn_scores_kernel<<<dim3(16, 16, B_ * H_), 256>>>(q, k, scores);
        softmax_kernel<<<B_ * H_ * T_, 128>>>(scores);
        attn_av_kernel<<<dim3(16, B_ * H_), 256>>>(scores, v, attn);

        conv_act_kernel<<<cE, 256>>>(attn, ah, al);
        mma_gemm_kernel<<<gEE, 256>>>(ah, al, wth + OWO + (size_t)l * SZ_EE, wtl + OWO + (size_t)l * SZ_EE,
                                      bo_l, tmp, BT, E_, E_, 0);
        add_ln_kernel<<<BT, 256>>>(x, tmp, ln1g + l * E_, ln1b + l * E_, x);

        conv_act_kernel<<<cE, 256>>>(x, ah, al);
        mma_gemm_kernel<<<gEF, 256>>>(ah, al, wth + OW1 + (size_t)l * E_ * FF_, wtl + OW1 + (size_t)l * E_ * FF_,
                                      b1_l, ff, BT, FF_, E_, 1);
        conv_act_kernel<<<cFF, 256>>>(ff, ah, al);
        mma_gemm_kernel<<<gEE, 256>>>(ah, al, wth + OW2 + (size_t)l * E_ * FF_, wtl + OW2 + (size_t)l * E_ * FF_,
                                      b2_l, tmp, BT, E_, FF_, 0);
        add_ln_kernel<<<BT, 256>>>(x, tmp, ln2g + l * E_, ln2b + l * E_, x);
    }

    add_ln_kernel<<<BT, 256>>>(x, nullptr, lnfg, lnfb, x);
    conv_act_kernel<<<cE, 256>>>(x, ah, al);
    mma_gemm_kernel<<<gHead, 256>>>(ah, al, wth + OHEAD, wtl + OHEAD, bhead, out, BT, V_, E_, 0);
}

// round 6
// speedup vs baseline: 1.9391x; 1.2447x over previous
#include <cuda_runtime.h>
#include <cuda_bf16.h>
#include <math.h>
#include <stdint.h>

#define B_  4
#define T_  1024
#define E_  1024
#define H_  16
#define HD  64
#define L_  6
#define FF_ 4096
#define V_  32000
#define BT  (B_ * T_)
#define E3  (3 * E_)

#define SZ_EE ((size_t)E_ * E_)
// transposed bf16 weight planes: fused QKV per layer [3E][E], then O, W1, W2, head
#define OQKV  ((size_t)0)                       // 6 layers * 3EE
#define OWO   ((size_t)18 * SZ_EE)
#define OW1   ((size_t)24 * SZ_EE)
#define OW2   ((size_t)48 * SZ_EE)
#define OHEAD ((size_t)72 * SZ_EE)
#define WTOT  (OHEAD + (size_t)E_ * V_)

// ---------------- device scratch (static, no allocations) ----------------
__device__ float g_x[BT * E_];
__device__ float g_qkv[(size_t)BT * E3];
__device__ float g_tmp[BT * E_];
__device__ float g_scores[(size_t)B_ * H_ * T_ * T_];
__device__ float g_bqkv[L_ * E3];
__device__ __nv_bfloat16 g_wth[WTOT];
__device__ __nv_bfloat16 g_wtl[WTOT];
__device__ __nv_bfloat16 g_ah[(size_t)BT * E_];    // x / attn hi (reused)
__device__ __nv_bfloat16 g_al[(size_t)BT * E_];
__device__ __nv_bfloat16 g_ffh[(size_t)BT * FF_];
__device__ __nv_bfloat16 g_ffl[(size_t)BT * FF_];

// ---------------- helpers ----------------
__device__ __forceinline__ uint32_t smem_u32(const void* p) {
    uint32_t a;
    asm("{ .reg .u64 t; cvta.to.shared.u64 t, %1; cvt.u32.u64 %0, t; }" : "=r"(a) : "l"(p));
    return a;
}
__device__ __forceinline__ float warpSum(float v) {
    #pragma unroll
    for (int o = 16; o > 0; o >>= 1) v += __shfl_xor_sync(0xffffffffu, v, o);
    return v;
}
__device__ __forceinline__ float warpMax(float v) {
    #pragma unroll
    for (int o = 16; o > 0; o >>= 1) v = fmaxf(v, __shfl_xor_sync(0xffffffffu, v, o));
    return v;
}
__device__ __forceinline__ void bsplit(float x, __nv_bfloat16& h, __nv_bfloat16& l) {
    h = __float2bfloat16(x);
    l = __float2bfloat16(x - __bfloat162float(h));
}
__device__ __forceinline__ unsigned pack2(__nv_bfloat16 a, __nv_bfloat16 b) {
    return (unsigned)__bfloat16_as_ushort(a) | ((unsigned)__bfloat16_as_ushort(b) << 16);
}
__device__ __forceinline__ void ldsm4(uint32_t* r, uint32_t addr) {
    asm volatile("ldmatrix.sync.aligned.m8n8.x4.shared.b16 {%0,%1,%2,%3}, [%4];"
                 : "=r"(r[0]), "=r"(r[1]), "=r"(r[2]), "=r"(r[3]) : "r"(addr));
}
__device__ __forceinline__ void cpa16(uint32_t dst, const void* src) {
    asm volatile("cp.async.cg.shared.global [%0], [%1], 16;" :: "r"(dst), "l"(src));
}
__device__ __forceinline__ void mma16816(float* c, const uint32_t* a, uint32_t b0, uint32_t b1) {
    asm volatile(
        "mma.sync.aligned.m16n8k16.row.col.f32.bf16.bf16.f32 "
        "{%0,%1,%2,%3}, {%4,%5,%6,%7}, {%8,%9}, {%0,%1,%2,%3};\n"
        : "+f"(c[0]), "+f"(c[1]), "+f"(c[2]), "+f"(c[3])
        : "r"(a[0]), "r"(a[1]), "r"(a[2]), "r"(a[3]), "r"(b0), "r"(b1));
}

// ---------------- embedding: x + hi/lo split ----------------
__global__ void embed_kernel(const int* __restrict__ idx,
                             const float* __restrict__ tok,
                             const float* __restrict__ pos,
                             float* __restrict__ x,
                             __nv_bfloat16* __restrict__ xh,
                             __nv_bfloat16* __restrict__ xl) {
    int bt = blockIdx.x;
    int t  = bt & (T_ - 1);
    int id = idx[bt];
    int c  = threadIdx.x;
    float4 a = ((const float4*)(tok + (size_t)id * E_))[c];
    float4 p = ((const float4*)(pos + (size_t)t  * E_))[c];
    a.x += p.x; a.y += p.y; a.z += p.z; a.w += p.w;
    ((float4*)(x + (size_t)bt * E_))[c] = a;
    __nv_bfloat16 h0,h1,h2,h3,l0,l1,l2,l3;
    bsplit(a.x,h0,l0); bsplit(a.y,h1,l1); bsplit(a.z,h2,l2); bsplit(a.w,h3,l3);
    uint2 hh, ll;
    hh.x = pack2(h0,h1); hh.y = pack2(h2,h3);
    ll.x = pack2(l0,l1); ll.y = pack2(l2,l3);
    ((uint2*)(xh + (size_t)bt * E_))[c] = hh;
    ((uint2*)(xl + (size_t)bt * E_))[c] = ll;
}

// ---------------- bias pack for fused QKV ----------------
__global__ void pack_bias_kernel(const float* __restrict__ bq,
                                 const float* __restrict__ bk,
                                 const float* __restrict__ bv,
                                 float* __restrict__ o) {
    int l = blockIdx.y;
    int i = blockIdx.x * 256 + threadIdx.x;     // 0..3071
    int w = i >> 10, c = i & 1023;
    const float* s = (w == 0) ? bq : (w == 1) ? bk : bv;
    o[l * E3 + i] = s[l * E_ + c];
}

// ---------------- weight transpose + bf16 hi/lo split ----------------
// W: [K,N] f32 (layer via blockIdx.z, input stride K*N) -> Th/Tl [N][K], layer out-stride lso
__global__ void tconv_kernel(const float* __restrict__ W,
                             __nv_bfloat16* __restrict__ Th,
                             __nv_bfloat16* __restrict__ Tl,
                             int K, int N, size_t lso) {
    __shared__ float tile[32][33];
    const float* Wl = W + (size_t)blockIdx.z * K * N;
    __nv_bfloat16* Thl = Th + (size_t)blockIdx.z * lso;
    __nv_bfloat16* Tll = Tl + (size_t)blockIdx.z * lso;
    int n0 = blockIdx.x * 32, k0 = blockIdx.y * 32;
    int tx = threadIdx.x & 31, ty = threadIdx.x >> 5;
    #pragma unroll
    for (int i = 0; i < 4; i++)
        tile[ty + i * 8][tx] = Wl[(size_t)(k0 + ty + i * 8) * N + n0 + tx];
    __syncthreads();
    #pragma unroll
    for (int i = 0; i < 4; i++) {
        int n = n0 + ty + i * 8;
        int k = k0 + tx;
        __nv_bfloat16 h, l;
        bsplit(tile[tx][ty + i * 8], h, l);
        Thl[(size_t)n * K + k] = h;
        Tll[(size_t)n * K + k] = l;
    }
}

// ================= mma.sync GEMM, 3-stage cp.async pipeline =================
// C = A[M,K] * (B[N,K])^T + bias, 3-pass hi/lo bf16. CTA 128x128, K-chunk 32.
// smem per stage: A(128x32 hi+lo) + B(128x32 hi+lo), 144B row pitch
// (hi at byte 0..63, lo at 80..143); 3 stages = 110,592 B.
#define ST_PITCH 144
#define ST_TENS  (128 * ST_PITCH)    // 18432
#define ST_BYTES (2 * ST_TENS)       // 36864
#define GEMM_SMEM (3 * ST_BYTES)

template<int RELU, int WF32, int WBF16>
__global__ __launch_bounds__(256, 1)
void mma_gemm_kernel(const __nv_bfloat16* __restrict__ Ah, const __nv_bfloat16* __restrict__ Al,
                     const __nv_bfloat16* __restrict__ Bh, const __nv_bfloat16* __restrict__ Bl,
                     const float* __restrict__ bias, float* __restrict__ Cf,
                     __nv_bfloat16* __restrict__ Ch, __nv_bfloat16* __restrict__ Cl,
                     int M, int N, int K) {
    extern __shared__ char smem_raw[];
    uint32_t sb = smem_u32(smem_raw);

    int tid = threadIdx.x, wid = tid >> 5, lane = tid & 31;
    int g = lane >> 2, tq = lane & 3;
    int wm = (wid >> 2) * 64;       // 2 x 4 warps, warp tile 64x32
    int wn = (wid & 3) * 32;
    int bm = blockIdx.y * 128, bn = blockIdx.x * 128;

    const __nv_bfloat16* baseA[2] = { Ah + (size_t)bm * K, Al + (size_t)bm * K };
    const __nv_bfloat16* baseB[2] = { Bh + (size_t)bn * K, Bl + (size_t)bn * K };

    int nch = K / 32;

    auto load_chunk = [&](int ci, int s) {
        uint32_t st = sb + s * ST_BYTES;
        int k0 = ci * 32;
        #pragma unroll
        for (int j = 0; j < 8; j++) {
            int seg = tid + j * 256;           // 0..2047
            int tens  = seg >> 10;             // 0=A, 1=B
            int rem   = seg & 1023;
            int row   = rem >> 3;
            int cc    = rem & 7;
            int plane = cc >> 2;               // 0=hi, 1=lo
            int kc    = cc & 3;                // 16B chunk (8 elems)
            uint32_t dst = st + tens * ST_TENS + row * ST_PITCH + plane * 80 + kc * 16;
            const __nv_bfloat16* src =
                (tens ? baseB[plane] : baseA[plane]) + (size_t)row * K + k0 + kc * 8;
            cpa16(dst, src);
        }
        asm volatile("cp.async.commit_group;" ::: "memory");
    };

    float acc[4][4][4];
    #pragma unroll
    for (int a = 0; a < 4; a++)
        #pragma unroll
        for (int b = 0; b < 4; b++)
            #pragma unroll
            for (int c = 0; c < 4; c++) acc[a][b][c] = 0.f;

    load_chunk(0, 0);
    load_chunk(1, 1);
    load_chunk(2, 2);

    for (int i = 0; i < nch; i++) {
        int rem = nch - 1 - i;
        if (rem >= 2)      asm volatile("cp.async.wait_group 2;" ::: "memory");
        else if (rem == 1) asm volatile("cp.async.wait_group 1;" ::: "memory");
        else               asm volatile("cp.async.wait_group 0;" ::: "memory");
        __syncthreads();

        uint32_t stA = sb + (i % 3) * ST_BYTES;
        uint32_t stB = stA + ST_TENS;

        // per-lane ldmatrix source rows
        int arow  = wm + (lane & 15);
        int akoff = ((lane >> 4) << 3);
        int brow  = wn + (lane & 7) + ((lane >> 4) << 3);
        int bkoff = (lane & 8);

        #pragma unroll
        for (int kk = 0; kk < 32; kk += 16) {
            uint32_t ah[4][4], al2[4][4], bh[2][4], bl2[2][4];
            #pragma unroll
            for (int mi = 0; mi < 4; mi++) {
                uint32_t ad = stA + (arow + mi * 16) * ST_PITCH + (kk + akoff) * 2;
                ldsm4(ah[mi], ad);
                ldsm4(al2[mi], ad + 80);
            }
            #pragma unroll
            for (int nb = 0; nb < 2; nb++) {
                uint32_t bd = stB + (brow + nb * 16) * ST_PITCH + (kk + bkoff) * 2;
                ldsm4(bh[nb], bd);
                ldsm4(bl2[nb], bd + 80);
            }
            #pragma unroll
            for (int mi = 0; mi < 4; mi++)
                #pragma unroll
                for (int ni = 0; ni < 4; ni++) {
                    int nb = ni >> 1, s2 = (ni & 1) * 2;
                    mma16816(acc[mi][ni], ah[mi],  bh[nb][s2],  bh[nb][s2 + 1]);
                    mma16816(acc[mi][ni], ah[mi],  bl2[nb][s2], bl2[nb][s2 + 1]);
                    mma16816(acc[mi][ni], al2[mi], bh[nb][s2],  bh[nb][s2 + 1]);
                }
        }
        __syncthreads();
        if (i + 3 < nch) load_chunk(i + 3, i % 3);
    }

    // epilogue
    #pragma unroll
    for (int mi = 0; mi < 4; mi++) {
        int r0 = bm + wm + mi * 16 + g;
        #pragma unroll
        for (int ni = 0; ni < 4; ni++) {
            int c0 = bn + wn + ni * 8 + 2 * tq;
            float bx = bias[c0], by = bias[c0 + 1];
            float2 v0, v1;
            v0.x = acc[mi][ni][0] + bx; v0.y = acc[mi][ni][1] + by;
            v1.x = acc[mi][ni][2] + bx; v1.y = acc[mi][ni][3] + by;
            if (RELU) {
                v0.x = fmaxf(v0.x, 0.f); v0.y = fmaxf(v0.y, 0.f);
                v1.x = fmaxf(v1.x, 0.f); v1.y = fmaxf(v1.y, 0.f);
            }
            if (WF32) {
                *(float2*)(Cf + (size_t)r0 * N + c0)       = v0;
                *(float2*)(Cf + (size_t)(r0 + 8) * N + c0) = v1;
            }
            if (WBF16) {
                __nv_bfloat16 h0, h1, l0, l1;
                bsplit(v0.x, h0, l0); bsplit(v0.y, h1, l1);
                *(uint32_t*)(Ch + (size_t)r0 * N + c0) = pack2(h0, h1);
                *(uint32_t*)(Cl + (size_t)r0 * N + c0) = pack2(l0, l1);
                bsplit(v1.x, h0, l0); bsplit(v1.y, h1, l1);
                *(uint32_t*)(Ch + (size_t)(r0 + 8) * N + c0) = pack2(h0, h1);
                *(uint32_t*)(Cl + (size_t)(r0 + 8) * N + c0) = pack2(l0, l1);
            }
        }
    }
}

// ---------------- attention scores: S = QK^T/8, causal (fp32) ----------------
// Q/K come from fused qkv buffer with row stride ld.
__global__ void attn_scores_kernel(const float* __restrict__ Q,
                                   const float* __restrict__ Kb,
                                   float* __restrict__ S, int ld) {
    int jt = blockIdx.x, it = blockIdx.y, bh = blockIdx.z;
    if (jt > it) return;
    int b = bh >> 4, h = bh & 15;

    __shared__ float Qs[64][65];
    __shared__ float Ks[64][65];
    int tid = threadIdx.x;
    #pragma unroll
    for (int p = 0; p < 4; p++) {
        int r = p * 16 + (tid >> 4);
        int c = (tid & 15) * 4;
        float4 qv = *(const float4*)(Q + ((size_t)(b * T_ + it * 64 + r) * ld) + h * HD + c);
        Qs[r][c] = qv.x; Qs[r][c + 1] = qv.y; Qs[r][c + 2] = qv.z; Qs[r][c + 3] = qv.w;
        float4 kv = *(const float4*)(Kb + ((size_t)(b * T_ + jt * 64 + r) * ld) + h * HD + c);
        Ks[r][c] = kv.x; Ks[r][c + 1] = kv.y; Ks[r][c + 2] = kv.z; Ks[r][c + 3] = kv.w;
    }
    __syncthreads();

    int tx = tid & 15, ty = tid >> 4;
    float acc[4][4] = {};
    #pragma unroll 8
    for (int d = 0; d < 64; d++) {
        float rq[4], rk[4];
        #pragma unroll
        for (int ii = 0; ii < 4; ii++) rq[ii] = Qs[ty * 4 + ii][d];
        #pragma unroll
        for (int jj = 0; jj < 4; jj++) rk[jj] = Ks[tx * 4 + jj][d];
        #pragma unroll
        for (int ii = 0; ii < 4; ii++)
            #pragma unroll
            for (int jj = 0; jj < 4; jj++)
                acc[ii][jj] = fmaf(rq[ii], rk[jj], acc[ii][jj]);
    }

    #pragma unroll
    for (int ii = 0; ii < 4; ii++) {
        int ig = it * 64 + ty * 4 + ii;
        #pragma unroll
        for (int jj = 0; jj < 4; jj++) {
            int jg = jt * 64 + tx * 4 + jj;
            float v = acc[ii][jj] * 0.125f;
            if (jg > ig) v = -1e30f;
            S[((size_t)bh * T_ + ig) * T_ + jg] = v;
        }
    }
}

// ---------------- row softmax (triangular, in place) ----------------
__global__ void softmax_kernel(float* __restrict__ S) {
    int rid = blockIdx.x;
    int bh = rid >> 10, i = rid & 1023;
    float* row = S + ((size_t)bh * T_ + i) * T_;
    int n = i + 1;
    int t = threadIdx.x;

    float vals[8];
    float m = -1e30f;
    #pragma unroll
    for (int k = 0; k < 8; k++) {
        int j = t + k * 128;
        vals[k] = (j < n) ? row[j] : -1e30f;
        m = fmaxf(m, vals[k]);
    }
    __shared__ float sh[8];
    m = warpMax(m);
    int w = t >> 5, lane = t & 31;
    if (lane == 0) sh[w] = m;
    __syncthreads();
    if (w == 0) {
        float a = (lane < 4) ? sh[lane] : -1e30f;
        a = warpMax(a);
        if (lane == 0) sh[0] = a;
    }
    __syncthreads();
    float M = sh[0];

    float s = 0.f;
    #pragma unroll
    for (int k = 0; k < 8; k++) {
        int j = t + k * 128;
        if (j < n) { vals[k] = expf(vals[k] - M); s += vals[k]; }
    }
    __syncthreads();
    s = warpSum(s);
    if (lane == 0) sh[w] = s;
    __syncthreads();
    if (w == 0) {
        float a = (lane < 4) ? sh[lane] : 0.f;
        a = warpSum(a);
        if (lane == 0) sh[0] = a;
    }
    __syncthreads();
    float inv = 1.f / sh[0];

    #pragma unroll
    for (int k = 0; k < 8; k++) {
        int j = t + k * 128;
        if (j < n) row[j] = vals[k] * inv;
    }
}

// ---------------- O = P * V, writes hi/lo bf16 directly ----------------
__global__ void attn_av_kernel(const float* __restrict__ S,
                               const float* __restrict__ Vb, int ld,
                               __nv_bfloat16* __restrict__ Oh,
                               __nv_bfloat16* __restrict__ Ol) {
    int it = blockIdx.x, bh = blockIdx.y;
    int b = bh >> 4, h = bh & 15;
    __shared__ float Ps[64][65];
    __shared__ float Vs[64][65];
    int tid = threadIdx.x;
    int tx = tid & 15, ty = tid >> 4;
    float acc[4][4] = {};

    for (int jt = 0; jt <= it; jt++) {
        #pragma unroll
        for (int p = 0; p < 4; p++) {
            int r = p * 16 + (tid >> 4);
            int c = (tid & 15) * 4;
            int ig = it * 64 + r;
            int jg = jt * 64 + c;
            float4 s4 = *(const float4*)(S + ((size_t)bh * T_ + ig) * T_ + jg);
            Ps[r][c + 0] = (jg + 0 <= ig) ? s4.x : 0.f;
            Ps[r][c + 1] = (jg + 1 <= ig) ? s4.y : 0.f;
            Ps[r][c + 2] = (jg + 2 <= ig) ? s4.z : 0.f;
            Ps[r][c + 3] = (jg + 3 <= ig) ? s4.w : 0.f;
            float4 vv = *(const float4*)(Vb + ((size_t)(b * T_ + jt * 64 + r) * ld) + h * HD + c);
            Vs[r][c] = vv.x; Vs[r][c + 1] = vv.y; Vs[r][c + 2] = vv.z; Vs[r][c + 3] = vv.w;
        }
        __syncthreads();
        #pragma unroll 8
        for (int j = 0; j < 64; j++) {
            float rp[4], rv[4];
            #pragma unroll
            for (int ii = 0; ii < 4; ii++) rp[ii] = Ps[ty * 4 + ii][j];
            #pragma unroll
            for (int jj = 0; jj < 4; jj++) rv[jj] = Vs[j][tx * 4 + jj];
            #pragma unroll
            for (int ii = 0; ii < 4; ii++)
                #pragma unroll
                for (int jj = 0; jj < 4; jj++)
                    acc[ii][jj] = fmaf(rp[ii], rv[jj], acc[ii][jj]);
        }
        __syncthreads();
    }

    #pragma unroll
    for (int ii = 0; ii < 4; ii++) {
        int ig = it * 64 + ty * 4 + ii;
        size_t off = (size_t)(b * T_ + ig) * E_ + h * HD + tx * 4;
        __nv_bfloat16 h0,h1,h2,h3,l0,l1,l2,l3;
        bsplit(acc[ii][0], h0, l0); bsplit(acc[ii][1], h1, l1);
        bsplit(acc[ii][2], h2, l2); bsplit(acc[ii][3], h3, l3);
        uint2 hh, ll;
        hh.x = pack2(h0,h1); hh.y = pack2(h2,h3);
        ll.x = pack2(l0,l1); ll.y = pack2(l2,l3);
        *(uint2*)(Oh + off) = hh;
        *(uint2*)(Ol + off) = ll;
    }
}

// ---------------- out = LayerNorm(in (+ res)); writes fp32 + hi/lo bf16 ----------------
__global__ void add_ln_kernel(const float* __restrict__ in,
                              const float* __restrict__ res,
                              const float* __restrict__ g,
                              const float* __restrict__ bb,
                              float* __restrict__ out,
                              __nv_bfloat16* __restrict__ oh,
                              __nv_bfloat16* __restrict__ ol) {
    int row = blockIdx.x;
    int t = threadIdx.x;
    float4 v = ((const float4*)(in + (size_t)row * E_))[t];
    if (res) {
        float4 r = ((const float4*)(res + (size_t)row * E_))[t];
        v.x += r.x; v.y += r.y; v.z += r.z; v.w += r.w;
    }
    float s  = v.x + v.y + v.z + v.w;
    float s2 = v.x * v.x + v.y * v.y + v.z * v.z + v.w * v.w;

    __shared__ float sh[16];
    s = warpSum(s); s2 = warpSum(s2);
    int w = t >> 5, lane = t & 31;
    if (lane == 0) { sh[w] = s; sh[w + 8] = s2; }
    __syncthreads();
    if (w == 0) {
        float a  = (lane < 8) ? sh[lane] : 0.f;
        a = warpSum(a);
        float a2 = (lane < 8) ? sh[lane + 8] : 0.f;
        a2 = warpSum(a2);
        if (lane == 0) { sh[0] = a; sh[8] = a2; }
    }
    __syncthreads();
    float mean = sh[0] * (1.f / E_);
    float var  = sh[8] * (1.f / E_) - mean * mean;
    float rstd = rsqrtf(var + 1e-5f);

    float4 gv = ((const float4*)g)[t];
    float4 bv = ((const float4*)bb)[t];
    float4 o;
    o.x = (v.x - mean) * rstd * gv.x + bv.x;
    o.y = (v.y - mean) * rstd * gv.y + bv.y;
    o.z = (v.z - mean) * rstd * gv.z + bv.z;
    o.w = (v.w - mean) * rstd * gv.w + bv.w;
    ((float4*)(out + (size_t)row * E_))[t] = o;

    __nv_bfloat16 h0,h1,h2,h3,l0,l1,l2,l3;
    bsplit(o.x,h0,l0); bsplit(o.y,h1,l1); bsplit(o.z,h2,l2); bsplit(o.w,h3,l3);
    uint2 hh, ll;
    hh.x = pack2(h0,h1); hh.y = pack2(h2,h3);
    ll.x = pack2(l0,l1); ll.y = pack2(l2,l3);
    ((uint2*)(oh + (size_t)row * E_))[t] = hh;
    ((uint2*)(ol + (size_t)row * E_))[t] = ll;
}

// ---------------- host launch ----------------
extern "C" void kernel_launch(void* const* d_in, const int* in_sizes, int n_in,
                              void* d_out, int out_size) {
    const int*   idx   = (const int*)  d_in[0];
    const float* tok   = (const float*)d_in[1];
    const float* pos   = (const float*)d_in[2];
    const float* Wq    = (const float*)d_in[3];
    const float* bq    = (const float*)d_in[4];
    const float* Wk    = (const float*)d_in[5];
    const float* bk    = (const float*)d_in[6];
    const float* Wv    = (const float*)d_in[7];
    const float* bv    = (const float*)d_in[8];
    const float* Wo    = (const float*)d_in[9];
    const float* bo    = (const float*)d_in[10];
    const float* W1    = (const float*)d_in[11];
    const float* b1    = (const float*)d_in[12];
    const float* W2    = (const float*)d_in[13];
    const float* b2    = (const float*)d_in[14];
    const float* ln1g  = (const float*)d_in[15];
    const float* ln1b  = (const float*)d_in[16];
    const float* ln2g  = (const float*)d_in[17];
    const float* ln2b  = (const float*)d_in[18];
    const float* lnfg  = (const float*)d_in[19];
    const float* lnfb  = (const float*)d_in[20];
    const float* Whead = (const float*)d_in[21];
    const float* bhead = (const float*)d_in[22];
    float* out = (float*)d_out;

    float *x, *qkv, *tmp, *scores, *bqkv;
    __nv_bfloat16 *wth, *wtl, *ah, *al, *ffh, *ffl;
    cudaGetSymbolAddress((void**)&x,      g_x);
    cudaGetSymbolAddress((void**)&qkv,    g_qkv);
    cudaGetSymbolAddress((void**)&tmp,    g_tmp);
    cudaGetSymbolAddress((void**)&scores, g_scores);
    cudaGetSymbolAddress((void**)&bqkv,   g_bqkv);
    cudaGetSymbolAddress((void**)&wth,    g_wth);
    cudaGetSymbolAddress((void**)&wtl,    g_wtl);
    cudaGetSymbolAddress((void**)&ah,     g_ah);
    cudaGetSymbolAddress((void**)&al,     g_al);
    cudaGetSymbolAddress((void**)&ffh,    g_ffh);
    cudaGetSymbolAddress((void**)&ffl,    g_ffl);

    cudaFuncSetAttribute(mma_gemm_kernel<0,1,0>,
                         cudaFuncAttributeMaxDynamicSharedMemorySize, GEMM_SMEM);
    cudaFuncSetAttribute(mma_gemm_kernel<1,0,1>,
                         cudaFuncAttributeMaxDynamicSharedMemorySize, GEMM_SMEM);

    // --- weight transpose + split into fused layout ---
    tconv_kernel<<<dim3(E_ / 32,  E_ / 32,  L_), 256>>>(Wq, wth + OQKV,             wtl + OQKV,             E_, E_, 3 * SZ_EE);
    tconv_kernel<<<dim3(E_ / 32,  E_ / 32,  L_), 256>>>(Wk, wth + OQKV + SZ_EE,     wtl + OQKV + SZ_EE,     E_, E_, 3 * SZ_EE);
    tconv_kernel<<<dim3(E_ / 32,  E_ / 32,  L_), 256>>>(Wv, wth + OQKV + 2 * SZ_EE, wtl + OQKV + 2 * SZ_EE, E_, E_, 3 * SZ_EE);
    tconv_kernel<<<dim3(E_ / 32,  E_ / 32,  L_), 256>>>(Wo, wth + OWO,  wtl + OWO,  E_,  E_,  SZ_EE);
    tconv_kernel<<<dim3(FF_ / 32, E_ / 32,  L_), 256>>>(W1, wth + OW1,  wtl + OW1,  E_,  FF_, (size_t)E_ * FF_);
    tconv_kernel<<<dim3(E_ / 32,  FF_ / 32, L_), 256>>>(W2, wth + OW2,  wtl + OW2,  FF_, E_,  (size_t)E_ * FF_);
    tconv_kernel<<<dim3(V_ / 32,  E_ / 32,  1 ), 256>>>(Whead, wth + OHEAD, wtl + OHEAD, E_, V_, 0);
    pack_bias_kernel<<<dim3(12, L_), 256>>>(bq, bk, bv, bqkv);

    embed_kernel<<<BT, 256>>>(idx, tok, pos, x, ah, al);

    dim3 gQKV(E3 / 128, BT / 128);
    dim3 gEE(E_ / 128, BT / 128);
    dim3 gEF(FF_ / 128, BT / 128);
    dim3 gHead(V_ / 128, BT / 128);

    for (int l = 0; l < L_; l++) {
        // fused QKV projection -> qkv [BT][3072] fp32
        mma_gemm_kernel<0,1,0><<<gQKV, 256, GEMM_SMEM>>>(
            ah, al, wth + OQKV + (size_t)l * 3 * SZ_EE, wtl + OQKV + (size_t)l * 3 * SZ_EE,
            bqkv + l * E3, qkv, nullptr, nullptr, BT, E3, E_);

        attn_scores_kernel<<<dim3(16, 16, B_ * H_), 256>>>(qkv, qkv + E_, scores, E3);
        softmax_kernel<<<B_ * H_ * T_, 128>>>(scores);
        attn_av_kernel<<<dim3(16, B_ * H_), 256>>>(scores, qkv + 2 * E_, E3, ah, al);

        mma_gemm_kernel<0,1,0><<<gEE, 256, GEMM_SMEM>>>(
            ah, al, wth + OWO + (size_t)l * SZ_EE, wtl + OWO + (size_t)l * SZ_EE,
            bo + l * E_, tmp, nullptr, nullptr, BT, E_, E_);
        add_ln_kernel<<<BT, 256>>>(x, tmp, ln1g + l * E_, ln1b + l * E_, x, ah, al);

        mma_gemm_kernel<1,0,1><<<gEF, 256, GEMM_SMEM>>>(
            ah, al, wth + OW1 + (size_t)l * E_ * FF_, wtl + OW1 + (size_t)l * E_ * FF_,
            b1 + l * FF_, nullptr, ffh, ffl, BT, FF_, E_);
        mma_gemm_kernel<0,1,0><<<gEE, 256, GEMM_SMEM>>>(
            ffh, ffl, wth + OW2 + (size_t)l * E_ * FF_, wtl + OW2 + (size_t)l * E_ * FF_,
            b2 + l * E_, tmp, nullptr, nullptr, BT, E_, FF_);
        add_ln_kernel<<<BT, 256>>>(x, tmp, ln2g + l * E_, ln2b + l * E_, x, ah, al);
    }

    add_ln_kernel<<<BT, 256>>>(x, nullptr, lnfg, lnfb, x, ah, al);
    mma_gemm_kernel<0,1,0><<<gHead, 256, GEMM_SMEM>>>(
        ah, al, wth + OHEAD, wtl + OHEAD, bhead, out, nullptr, nullptr, BT, V_, E_);
}

// round 7
// speedup vs baseline: 2.7085x; 1.3968x over previous
#include <cuda_runtime.h>
#include <cuda_bf16.h>
#include <math.h>
#include <stdint.h>

#define B_  4
#define T_  1024
#define E_  1024
#define H_  16
#define HD  64
#define L_  6
#define FF_ 4096
#define V_  32000
#define BT  (B_ * T_)
#define E3  (3 * E_)

#define SZ_EE ((size_t)E_ * E_)
// transposed fp32(tf32-rounded) weights: fused QKV per layer [3E][E], then O, W1, W2, head
#define OQKV  ((size_t)0)
#define OWO   ((size_t)18 * SZ_EE)
#define OW1   ((size_t)24 * SZ_EE)
#define OW2   ((size_t)48 * SZ_EE)
#define OHEAD ((size_t)72 * SZ_EE)
#define WTOT  (OHEAD + (size_t)E_ * V_)

// ---------------- device scratch (static, no allocations) ----------------
__device__ float g_x[BT * E_];                    // residual stream (full fp32)
__device__ float g_xr[BT * E_];                   // tf32-rounded GEMM input (reused)
__device__ float g_qkv[(size_t)BT * E3];
__device__ float g_tmp[BT * E_];
__device__ float g_ffr[(size_t)BT * FF_];
__device__ float g_scores[(size_t)B_ * H_ * T_ * T_];
__device__ float g_bqkv[L_ * E3];
__device__ float g_wt[WTOT];

// ---------------- helpers ----------------
__device__ __forceinline__ uint32_t smem_u32(const void* p) {
    uint32_t a;
    asm("{ .reg .u64 t; cvta.to.shared.u64 t, %1; cvt.u32.u64 %0, t; }" : "=r"(a) : "l"(p));
    return a;
}
__device__ __forceinline__ float warpSum(float v) {
    #pragma unroll
    for (int o = 16; o > 0; o >>= 1) v += __shfl_xor_sync(0xffffffffu, v, o);
    return v;
}
__device__ __forceinline__ float warpMax(float v) {
    #pragma unroll
    for (int o = 16; o > 0; o >>= 1) v = fmaxf(v, __shfl_xor_sync(0xffffffffu, v, o));
    return v;
}
__device__ __forceinline__ float tf32r(float x) {
    float y;
    asm("cvt.rna.tf32.f32 %0, %1;" : "=f"(y) : "f"(x));
    return y;
}
__device__ __forceinline__ void ldsm4(uint32_t* r, uint32_t addr) {
    asm volatile("ldmatrix.sync.aligned.m8n8.x4.shared.b16 {%0,%1,%2,%3}, [%4];"
                 : "=r"(r[0]), "=r"(r[1]), "=r"(r[2]), "=r"(r[3]) : "r"(addr));
}
__device__ __forceinline__ void cpa16(uint32_t dst, const void* src) {
    asm volatile("cp.async.cg.shared.global [%0], [%1], 16;" :: "r"(dst), "l"(src));
}
__device__ __forceinline__ void mma_tf32(float* c, const uint32_t* a, uint32_t b0, uint32_t b1) {
    asm volatile(
        "mma.sync.aligned.m16n8k8.row.col.f32.tf32.tf32.f32 "
        "{%0,%1,%2,%3}, {%4,%5,%6,%7}, {%8,%9}, {%0,%1,%2,%3};\n"
        : "+f"(c[0]), "+f"(c[1]), "+f"(c[2]), "+f"(c[3])
        : "r"(a[0]), "r"(a[1]), "r"(a[2]), "r"(a[3]), "r"(b0), "r"(b1));
}

// ---------------- embedding: x + tf32-rounded copy ----------------
__global__ void embed_kernel(const int* __restrict__ idx,
                             const float* __restrict__ tok,
                             const float* __restrict__ pos,
                             float* __restrict__ x,
                             float* __restrict__ xr) {
    int bt = blockIdx.x;
    int t  = bt & (T_ - 1);
    int id = idx[bt];
    int c  = threadIdx.x;
    float4 a = ((const float4*)(tok + (size_t)id * E_))[c];
    float4 p = ((const float4*)(pos + (size_t)t  * E_))[c];
    a.x += p.x; a.y += p.y; a.z += p.z; a.w += p.w;
    ((float4*)(x + (size_t)bt * E_))[c] = a;
    float4 r;
    r.x = tf32r(a.x); r.y = tf32r(a.y); r.z = tf32r(a.z); r.w = tf32r(a.w);
    ((float4*)(xr + (size_t)bt * E_))[c] = r;
}

// ---------------- bias pack for fused QKV ----------------
__global__ void pack_bias_kernel(const float* __restrict__ bq,
                                 const float* __restrict__ bk,
                                 const float* __restrict__ bv,
                                 float* __restrict__ o) {
    int l = blockIdx.y;
    int i = blockIdx.x * 256 + threadIdx.x;
    int w = i >> 10, c = i & 1023;
    const float* s = (w == 0) ? bq : (w == 1) ? bk : bv;
    o[l * E3 + i] = s[l * E_ + c];
}

// ---------------- weight transpose + tf32 round ----------------
// W: [K,N] f32 (layer via blockIdx.z) -> T [N][K] tf32-rounded fp32, layer out-stride lso
__global__ void tconv_kernel(const float* __restrict__ W,
                             float* __restrict__ To,
                             int K, int N, size_t lso) {
    __shared__ float tile[32][33];
    const float* Wl = W + (size_t)blockIdx.z * K * N;
    float* Tol = To + (size_t)blockIdx.z * lso;
    int n0 = blockIdx.x * 32, k0 = blockIdx.y * 32;
    int tx = threadIdx.x & 31, ty = threadIdx.x >> 5;
    #pragma unroll
    for (int i = 0; i < 4; i++)
        tile[ty + i * 8][tx] = Wl[(size_t)(k0 + ty + i * 8) * N + n0 + tx];
    __syncthreads();
    #pragma unroll
    for (int i = 0; i < 4; i++) {
        int n = n0 + ty + i * 8;
        int k = k0 + tx;
        Tol[(size_t)n * K + k] = tf32r(tile[tx][ty + i * 8]);
    }
}

// ================= tf32 mma.sync GEMM, 3-stage cp.async pipeline =================
// C = A[M,K] * (Bt[N,K])^T + bias. A/Bt are tf32-rounded fp32. CTA 128x128, K-chunk 32.
// Stage: A 128x32 f32 (128B/row, XOR-swizzled 16B chunks) + same for B = 32KB; 3 stages.
#define STP 128
#define STT (128 * STP)          // 16384
#define STB (2 * STT)            // 32768
#define GSM (3 * STB)            // 98304

template<int RELU, int WF32, int WROUND>
__global__ __launch_bounds__(256, 1)
void tf32_gemm_kernel(const float* __restrict__ A, const float* __restrict__ Bt,
                      const float* __restrict__ bias,
                      float* __restrict__ Cf, float* __restrict__ Cr,
                      int M, int N, int K) {
    extern __shared__ char smem_raw[];
    uint32_t sb = smem_u32(smem_raw);

    int tid = threadIdx.x, wid = tid >> 5, lane = tid & 31;
    int g = lane >> 2, tq = lane & 3;
    int wm = (wid >> 2) * 64;      // 2 x 4 warps, warp tile 64x32
    int wn = (wid & 3) * 32;
    int bm = blockIdx.y * 128, bn = blockIdx.x * 128;

    const float* baseA = A  + (size_t)bm * K;
    const float* baseB = Bt + (size_t)bn * K;
    int nch = K / 32;

    auto load_chunk = [&](int ci, int s) {
        uint32_t st = sb + s * STB;
        int k0 = ci * 32;
        #pragma unroll
        for (int j = 0; j < 8; j++) {
            int seg  = tid + j * 256;          // 0..2047
            int tens = seg >> 10;              // 0=A, 1=B
            int rem  = seg & 1023;
            int row  = rem >> 3;
            int c    = rem & 7;                // 16B chunk
            uint32_t dst = st + tens * STT + row * STP + ((c ^ (row & 7)) << 4);
            const float* src = (tens ? baseB : baseA) + (size_t)row * K + k0 + c * 4;
            cpa16(dst, src);
        }
        asm volatile("cp.async.commit_group;" ::: "memory");
    };

    float acc[4][4][4];
    #pragma unroll
    for (int a = 0; a < 4; a++)
        #pragma unroll
        for (int b = 0; b < 4; b++)
            #pragma unroll
            for (int c = 0; c < 4; c++) acc[a][b][c] = 0.f;

    load_chunk(0, 0);
    load_chunk(1, 1);
    load_chunk(2, 2);

    // per-lane ldmatrix row/chunk offsets
    int arow_l = (lane & 7) + ((lane >> 3) & 1) * 8;   // A: tiles {r0-7,c0},{r8-15,c0},{r0-7,c1},{r8-15,c1}
    int acb    = (lane >> 4);
    int brow_l = (lane & 7) + ((lane >> 4) << 3);      // B: tiles {n0-7,c0},{n0-7,c1},{n8-15,c0},{n8-15,c1}
    int bcb    = (lane >> 3) & 1;

    for (int i = 0; i < nch; i++) {
        int rem = nch - 1 - i;
        if (rem >= 2)      asm volatile("cp.async.wait_group 2;" ::: "memory");
        else if (rem == 1) asm volatile("cp.async.wait_group 1;" ::: "memory");
        else               asm volatile("cp.async.wait_group 0;" ::: "memory");
        __syncthreads();

        uint32_t stA = sb + (i % 3) * STB;
        uint32_t stB = stA + STT;

        #pragma unroll
        for (int kk = 0; kk < 4; kk++) {        // 4 k8 steps per 32-K chunk
            uint32_t af[4][4], bf[2][4];
            #pragma unroll
            for (int mi = 0; mi < 4; mi++) {
                int r = wm + mi * 16 + arow_l;
                int c = kk * 2 + acb;
                ldsm4(af[mi], stA + r * STP + ((c ^ (r & 7)) << 4));
            }
            #pragma unroll
            for (int nb = 0; nb < 2; nb++) {
                int r = wn + nb * 16 + brow_l;
                int c = kk * 2 + bcb;
                ldsm4(bf[nb], stB + r * STP + ((c ^ (r & 7)) << 4));
            }
            #pragma unroll
            for (int mi = 0; mi < 4; mi++)
                #pragma unroll
                for (int ni = 0; ni < 4; ni++) {
                    int nb = ni >> 1, o = (ni & 1) * 2;
                    mma_tf32(acc[mi][ni], af[mi], bf[nb][o], bf[nb][o + 1]);
                }
        }
        __syncthreads();
        if (i + 3 < nch) load_chunk(i + 3, i % 3);
    }

    // epilogue
    #pragma unroll
    for (int mi = 0; mi < 4; mi++) {
        int r0 = bm + wm + mi * 16 + g;
        #pragma unroll
        for (int ni = 0; ni < 4; ni++) {
            int c0 = bn + wn + ni * 8 + 2 * tq;
            float bx = bias[c0], by = bias[c0 + 1];
            float2 v0, v1;
            v0.x = acc[mi][ni][0] + bx; v0.y = acc[mi][ni][1] + by;
            v1.x = acc[mi][ni][2] + bx; v1.y = acc[mi][ni][3] + by;
            if (RELU) {
                v0.x = fmaxf(v0.x, 0.f); v0.y = fmaxf(v0.y, 0.f);
                v1.x = fmaxf(v1.x, 0.f); v1.y = fmaxf(v1.y, 0.f);
            }
            if (WF32) {
                *(float2*)(Cf + (size_t)r0 * N + c0)       = v0;
                *(float2*)(Cf + (size_t)(r0 + 8) * N + c0) = v1;
            }
            if (WROUND) {
                float2 w0, w1;
                w0.x = tf32r(v0.x); w0.y = tf32r(v0.y);
                w1.x = tf32r(v1.x); w1.y = tf32r(v1.y);
                *(float2*)(Cr + (size_t)r0 * N + c0)       = w0;
                *(float2*)(Cr + (size_t)(r0 + 8) * N + c0) = w1;
            }
        }
    }
}

// ---------------- attention scores: S = QK^T/8, causal (fp32) ----------------
__global__ void attn_scores_kernel(const float* __restrict__ Q,
                                   const float* __restrict__ Kb,
                                   float* __restrict__ S, int ld) {
    int jt = blockIdx.x, it = blockIdx.y, bh = blockIdx.z;
    if (jt > it) return;
    int b = bh >> 4, h = bh & 15;

    __shared__ float Qs[64][65];
    __shared__ float Ks[64][65];
    int tid = threadIdx.x;
    #pragma unroll
    for (int p = 0; p < 4; p++) {
        int r = p * 16 + (tid >> 4);
        int c = (tid & 15) * 4;
        float4 qv = *(const float4*)(Q + ((size_t)(b * T_ + it * 64 + r) * ld) + h * HD + c);
        Qs[r][c] = qv.x; Qs[r][c + 1] = qv.y; Qs[r][c + 2] = qv.z; Qs[r][c + 3] = qv.w;
        float4 kv = *(const float4*)(Kb + ((size_t)(b * T_ + jt * 64 + r) * ld) + h * HD + c);
        Ks[r][c] = kv.x; Ks[r][c + 1] = kv.y; Ks[r][c + 2] = kv.z; Ks[r][c + 3] = kv.w;
    }
    __syncthreads();

    int tx = tid & 15, ty = tid >> 4;
    float acc[4][4] = {};
    #pragma unroll 8
    for (int d = 0; d < 64; d++) {
        float rq[4], rk[4];
        #pragma unroll
        for (int ii = 0; ii < 4; ii++) rq[ii] = Qs[ty * 4 + ii][d];
        #pragma unroll
        for (int jj = 0; jj < 4; jj++) rk[jj] = Ks[tx * 4 + jj][d];
        #pragma unroll
        for (int ii = 0; ii < 4; ii++)
            #pragma unroll
            for (int jj = 0; jj < 4; jj++)
                acc[ii][jj] = fmaf(rq[ii], rk[jj], acc[ii][jj]);
    }

    #pragma unroll
    for (int ii = 0; ii < 4; ii++) {
        int ig = it * 64 + ty * 4 + ii;
        #pragma unroll
        for (int jj = 0; jj < 4; jj++) {
            int jg = jt * 64 + tx * 4 + jj;
            float v = acc[ii][jj] * 0.125f;
            if (jg > ig) v = -1e30f;
            S[((size_t)bh * T_ + ig) * T_ + jg] = v;
        }
    }
}

// ---------------- row softmax (triangular, in place) ----------------
__global__ void softmax_kernel(float* __restrict__ S) {
    int rid = blockIdx.x;
    int bh = rid >> 10, i = rid & 1023;
    float* row = S + ((size_t)bh * T_ + i) * T_;
    int n = i + 1;
    int t = threadIdx.x;

    float vals[8];
    float m = -1e30f;
    #pragma unroll
    for (int k = 0; k < 8; k++) {
        int j = t + k * 128;
        vals[k] = (j < n) ? row[j] : -1e30f;
        m = fmaxf(m, vals[k]);
    }
    __shared__ float sh[8];
    m = warpMax(m);
    int w = t >> 5, lane = t & 31;
    if (lane == 0) sh[w] = m;
    __syncthreads();
    if (w == 0) {
        float a = (lane < 4) ? sh[lane] : -1e30f;
        a = warpMax(a);
        if (lane == 0) sh[0] = a;
    }
    __syncthreads();
    float M = sh[0];

    float s = 0.f;
    #pragma unroll
    for (int k = 0; k < 8; k++) {
        int j = t + k * 128;
        if (j < n) { vals[k] = expf(vals[k] - M); s += vals[k]; }
    }
    __syncthreads();
    s = warpSum(s);
    if (lane == 0) sh[w] = s;
    __syncthreads();
    if (w == 0) {
        float a = (lane < 4) ? sh[lane] : 0.f;
        a = warpSum(a);
        if (lane == 0) sh[0] = a;
    }
    __syncthreads();
    float inv = 1.f / sh[0];

    #pragma unroll
    for (int k = 0; k < 8; k++) {
        int j = t + k * 128;
        if (j < n) row[j] = vals[k] * inv;
    }
}

// ---------------- O = P * V, writes tf32-rounded fp32 ----------------
__global__ void attn_av_kernel(const float* __restrict__ S,
                               const float* __restrict__ Vb, int ld,
                               float* __restrict__ Or) {
    int it = blockIdx.x, bh = blockIdx.y;
    int b = bh >> 4, h = bh & 15;
    __shared__ float Ps[64][65];
    __shared__ float Vs[64][65];
    int tid = threadIdx.x;
    int tx = tid & 15, ty = tid >> 4;
    float acc[4][4] = {};

    for (int jt = 0; jt <= it; jt++) {
        #pragma unroll
        for (int p = 0; p < 4; p++) {
            int r = p * 16 + (tid >> 4);
            int c = (tid & 15) * 4;
            int ig = it * 64 + r;
            int jg = jt * 64 + c;
            float4 s4 = *(const float4*)(S + ((size_t)bh * T_ + ig) * T_ + jg);
            Ps[r][c + 0] = (jg + 0 <= ig) ? s4.x : 0.f;
            Ps[r][c + 1] = (jg + 1 <= ig) ? s4.y : 0.f;
            Ps[r][c + 2] = (jg + 2 <= ig) ? s4.z : 0.f;
            Ps[r][c + 3] = (jg + 3 <= ig) ? s4.w : 0.f;
            float4 vv = *(const float4*)(Vb + ((size_t)(b * T_ + jt * 64 + r) * ld) + h * HD + c);
            Vs[r][c] = vv.x; Vs[r][c + 1] = vv.y; Vs[r][c + 2] = vv.z; Vs[r][c + 3] = vv.w;
        }
        __syncthreads();
        #pragma unroll 8
        for (int j = 0; j < 64; j++) {
            float rp[4], rv[4];
            #pragma unroll
            for (int ii = 0; ii < 4; ii++) rp[ii] = Ps[ty * 4 + ii][j];
            #pragma unroll
            for (int jj = 0; jj < 4; jj++) rv[jj] = Vs[j][tx * 4 + jj];
            #pragma unroll
            for (int ii = 0; ii < 4; ii++)
                #pragma unroll
                for (int jj = 0; jj < 4; jj++)
                    acc[ii][jj] = fmaf(rp[ii], rv[jj], acc[ii][jj]);
        }
        __syncthreads();
    }

    #pragma unroll
    for (int ii = 0; ii < 4; ii++) {
        int ig = it * 64 + ty * 4 + ii;
        float4 o;
        o.x = tf32r(acc[ii][0]); o.y = tf32r(acc[ii][1]);
        o.z = tf32r(acc[ii][2]); o.w = tf32r(acc[ii][3]);
        *(float4*)(Or + (size_t)(b * T_ + ig) * E_ + h * HD + tx * 4) = o;
    }
}

// ---------------- out = LayerNorm(in (+ res)); writes fp32 + tf32-rounded ----------------
__global__ void add_ln_kernel(const float* __restrict__ in,
                              const float* __restrict__ res,
                              const float* __restrict__ g,
                              const float* __restrict__ bb,
                              float* __restrict__ out,
                              float* __restrict__ outr) {
    int row = blockIdx.x;
    int t = threadIdx.x;
    float4 v = ((const float4*)(in + (size_t)row * E_))[t];
    if (res) {
        float4 r = ((const float4*)(res + (size_t)row * E_))[t];
        v.x += r.x; v.y += r.y; v.z += r.z; v.w += r.w;
    }
    float s  = v.x + v.y + v.z + v.w;
    float s2 = v.x * v.x + v.y * v.y + v.z * v.z + v.w * v.w;

    __shared__ float sh[16];
    s = warpSum(s); s2 = warpSum(s2);
    int w = t >> 5, lane = t & 31;
    if (lane == 0) { sh[w] = s; sh[w + 8] = s2; }
    __syncthreads();
    if (w == 0) {
        float a  = (lane < 8) ? sh[lane] : 0.f;
        a = warpSum(a);
        float a2 = (lane < 8) ? sh[lane + 8] : 0.f;
        a2 = warpSum(a2);
        if (lane == 0) { sh[0] = a; sh[8] = a2; }
    }
    __syncthreads();
    float mean = sh[0] * (1.f / E_);
    float var  = sh[8] * (1.f / E_) - mean * mean;
    float rstd = rsqrtf(var + 1e-5f);

    float4 gv = ((const float4*)g)[t];
    float4 bv = ((const float4*)bb)[t];
    float4 o;
    o.x = (v.x - mean) * rstd * gv.x + bv.x;
    o.y = (v.y - mean) * rstd * gv.y + bv.y;
    o.z = (v.z - mean) * rstd * gv.z + bv.z;
    o.w = (v.w - mean) * rstd * gv.w + bv.w;
    ((float4*)(out + (size_t)row * E_))[t] = o;

    float4 r;
    r.x = tf32r(o.x); r.y = tf32r(o.y); r.z = tf32r(o.z); r.w = tf32r(o.w);
    ((float4*)(outr + (size_t)row * E_))[t] = r;
}

// ---------------- host launch ----------------
extern "C" void kernel_launch(void* const* d_in, const int* in_sizes, int n_in,
                              void* d_out, int out_size) {
    const int*   idx   = (const int*)  d_in[0];
    const float* tok   = (const float*)d_in[1];
    const float* pos   = (const float*)d_in[2];
    const float* Wq    = (const float*)d_in[3];
    const float* bq    = (const float*)d_in[4];
    const float* Wk    = (const float*)d_in[5];
    const float* bk    = (const float*)d_in[6];
    const float* Wv    = (const float*)d_in[7];
    const float* bv    = (const float*)d_in[8];
    const float* Wo    = (const float*)d_in[9];
    const float* bo    = (const float*)d_in[10];
    const float* W1    = (const float*)d_in[11];
    const float* b1    = (const float*)d_in[12];
    const float* W2    = (const float*)d_in[13];
    const float* b2    = (const float*)d_in[14];
    const float* ln1g  = (const float*)d_in[15];
    const float* ln1b  = (const float*)d_in[16];
    const float* ln2g  = (const float*)d_in[17];
    const float* ln2b  = (const float*)d_in[18];
    const float* lnfg  = (const float*)d_in[19];
    const float* lnfb  = (const float*)d_in[20];
    const float* Whead = (const float*)d_in[21];
    const float* bhead = (const float*)d_in[22];
    float* out = (float*)d_out;

    float *x, *xr, *qkv, *tmp, *ffr, *scores, *bqkv, *wt;
    cudaGetSymbolAddress((void**)&x,      g_x);
    cudaGetSymbolAddress((void**)&xr,     g_xr);
    cudaGetSymbolAddress((void**)&qkv,    g_qkv);
    cudaGetSymbolAddress((void**)&tmp,    g_tmp);
    cudaGetSymbolAddress((void**)&ffr,    g_ffr);
    cudaGetSymbolAddress((void**)&scores, g_scores);
    cudaGetSymbolAddress((void**)&bqkv,   g_bqkv);
    cudaGetSymbolAddress((void**)&wt,     g_wt);

    cudaFuncSetAttribute(tf32_gemm_kernel<0,1,0>,
                         cudaFuncAttributeMaxDynamicSharedMemorySize, GSM);
    cudaFuncSetAttribute(tf32_gemm_kernel<1,0,1>,
                         cudaFuncAttributeMaxDynamicSharedMemorySize, GSM);

    // --- weight transpose + tf32 round, fused QKV layout ---
    tconv_kernel<<<dim3(E_ / 32,  E_ / 32,  L_), 256>>>(Wq, wt + OQKV,             E_, E_, 3 * SZ_EE);
    tconv_kernel<<<dim3(E_ / 32,  E_ / 32,  L_), 256>>>(Wk, wt + OQKV + SZ_EE,     E_, E_, 3 * SZ_EE);
    tconv_kernel<<<dim3(E_ / 32,  E_ / 32,  L_), 256>>>(Wv, wt + OQKV + 2 * SZ_EE, E_, E_, 3 * SZ_EE);
    tconv_kernel<<<dim3(E_ / 32,  E_ / 32,  L_), 256>>>(Wo, wt + OWO,  E_,  E_,  SZ_EE);
    tconv_kernel<<<dim3(FF_ / 32, E_ / 32,  L_), 256>>>(W1, wt + OW1,  E_,  FF_, (size_t)E_ * FF_);
    tconv_kernel<<<dim3(E_ / 32,  FF_ / 32, L_), 256>>>(W2, wt + OW2,  FF_, E_,  (size_t)E_ * FF_);
    tconv_kernel<<<dim3(V_ / 32,  E_ / 32,  1 ), 256>>>(Whead, wt + OHEAD, E_, V_, 0);
    pack_bias_kernel<<<dim3(12, L_), 256>>>(bq, bk, bv, bqkv);

    embed_kernel<<<BT, 256>>>(idx, tok, pos, x, xr);

    dim3 gQKV(E3 / 128, BT / 128);
    dim3 gEE(E_ / 128, BT / 128);
    dim3 gEF(FF_ / 128, BT / 128);
    dim3 gHead(V_ / 128, BT / 128);

    for (int l = 0; l < L_; l++) {
        tf32_gemm_kernel<0,1,0><<<gQKV, 256, GSM>>>(
            xr, wt + OQKV + (size_t)l * 3 * SZ_EE, bqkv + l * E3,
            qkv, nullptr, BT, E3, E_);

        attn_scores_kernel<<<dim3(16, 16, B_ * H_), 256>>>(qkv, qkv + E_, scores, E3);
        softmax_kernel<<<B_ * H_ * T_, 128>>>(scores);
        attn_av_kernel<<<dim3(16, B_ * H_), 256>>>(scores, qkv + 2 * E_, E3, xr);

        tf32_gemm_kernel<0,1,0><<<gEE, 256, GSM>>>(
            xr, wt + OWO + (size_t)l * SZ_EE, bo + l * E_,
            tmp, nullptr, BT, E_, E_);
        add_ln_kernel<<<BT, 256>>>(x, tmp, ln1g + l * E_, ln1b + l * E_, x, xr);

        tf32_gemm_kernel<1,0,1><<<gEF, 256, GSM>>>(
            xr, wt + OW1 + (size_t)l * E_ * FF_, b1 + l * FF_,
            nullptr, ffr, BT, FF_, E_);
        tf32_gemm_kernel<0,1,0><<<gEE, 256, GSM>>>(
            ffr, wt + OW2 + (size_t)l * E_ * FF_, b2 + l * E_,
            tmp, nullptr, BT, E_, FF_);
        add_ln_kernel<<<BT, 256>>>(x, tmp, ln2g + l * E_, ln2b + l * E_, x, xr);
    }

    add_ln_kernel<<<BT, 256>>>(x, nullptr, lnfg, lnfb, x, xr);
    tf32_gemm_kernel<0,1,0><<<gHead, 256, GSM>>>(
        xr, wt + OHEAD, bhead, out, nullptr, BT, V_, E_);
}

// round 8
// speedup vs baseline: 3.5985x; 1.3286x over previous
#include <cuda_runtime.h>
#include <cuda_bf16.h>
#include <math.h>
#include <stdint.h>

#define B_  4
#define T_  1024
#define E_  1024
#define H_  16
#define HD  64
#define L_  6
#define FF_ 4096
#define V_  32000
#define BT  (B_ * T_)
#define E3  (3 * E_)

#define SZ_EE ((size_t)E_ * E_)
#define OQKV  ((size_t)0)
#define OWO   ((size_t)18 * SZ_EE)
#define OW1   ((size_t)24 * SZ_EE)
#define OW2   ((size_t)48 * SZ_EE)
#define OHEAD ((size_t)72 * SZ_EE)
#define WTOT  (OHEAD + (size_t)E_ * V_)

// ---------------- device scratch ----------------
__device__ float g_x[BT * E_];
__device__ float g_xr[BT * E_];
__device__ float g_qkv[(size_t)BT * E3];     // tf32-rounded QKV
__device__ float g_tmp[BT * E_];
__device__ float g_ffr[(size_t)BT * FF_];
__device__ float g_bqkv[L_ * E3];
__device__ float g_wt[WTOT];

// ---------------- helpers ----------------
__device__ __forceinline__ uint32_t smem_u32(const void* p) {
    uint32_t a;
    asm("{ .reg .u64 t; cvta.to.shared.u64 t, %1; cvt.u32.u64 %0, t; }" : "=r"(a) : "l"(p));
    return a;
}
__device__ __forceinline__ float warpSum(float v) {
    #pragma unroll
    for (int o = 16; o > 0; o >>= 1) v += __shfl_xor_sync(0xffffffffu, v, o);
    return v;
}
__device__ __forceinline__ float tf32r(float x) {
    float y;
    asm("cvt.rna.tf32.f32 %0, %1;" : "=f"(y) : "f"(x));
    return y;
}
__device__ __forceinline__ void ldsm4(uint32_t* r, uint32_t addr) {
    asm volatile("ldmatrix.sync.aligned.m8n8.x4.shared.b16 {%0,%1,%2,%3}, [%4];"
                 : "=r"(r[0]), "=r"(r[1]), "=r"(r[2]), "=r"(r[3]) : "r"(addr));
}
__device__ __forceinline__ void cpa16(uint32_t dst, const void* src) {
    asm volatile("cp.async.cg.shared.global [%0], [%1], 16;" :: "r"(dst), "l"(src));
}
__device__ __forceinline__ void mma_tf32(float* c, const uint32_t* a, uint32_t b0, uint32_t b1) {
    asm volatile(
        "mma.sync.aligned.m16n8k8.row.col.f32.tf32.tf32.f32 "
        "{%0,%1,%2,%3}, {%4,%5,%6,%7}, {%8,%9}, {%0,%1,%2,%3};\n"
        : "+f"(c[0]), "+f"(c[1]), "+f"(c[2]), "+f"(c[3])
        : "r"(a[0]), "r"(a[1]), "r"(a[2]), "r"(a[3]), "r"(b0), "r"(b1));
}

// ---------------- embedding ----------------
__global__ void embed_kernel(const int* __restrict__ idx,
                             const float* __restrict__ tok,
                             const float* __restrict__ pos,
                             float* __restrict__ x,
                             float* __restrict__ xr) {
    int bt = blockIdx.x;
    int t  = bt & (T_ - 1);
    int id = idx[bt];
    int c  = threadIdx.x;
    float4 a = ((const float4*)(tok + (size_t)id * E_))[c];
    float4 p = ((const float4*)(pos + (size_t)t  * E_))[c];
    a.x += p.x; a.y += p.y; a.z += p.z; a.w += p.w;
    ((float4*)(x + (size_t)bt * E_))[c] = a;
    float4 r;
    r.x = tf32r(a.x); r.y = tf32r(a.y); r.z = tf32r(a.z); r.w = tf32r(a.w);
    ((float4*)(xr + (size_t)bt * E_))[c] = r;
}

// ---------------- bias pack for fused QKV ----------------
__global__ void pack_bias_kernel(const float* __restrict__ bq,
                                 const float* __restrict__ bk,
                                 const float* __restrict__ bv,
                                 float* __restrict__ o) {
    int l = blockIdx.y;
    int i = blockIdx.x * 256 + threadIdx.x;
    int w = i >> 10, c = i & 1023;
    const float* s = (w == 0) ? bq : (w == 1) ? bk : bv;
    o[l * E3 + i] = s[l * E_ + c];
}

// ---------------- weight transpose + tf32 round ----------------
__global__ void tconv_kernel(const float* __restrict__ W,
                             float* __restrict__ To,
                             int K, int N, size_t lso) {
    __shared__ float tile[32][33];
    const float* Wl = W + (size_t)blockIdx.z * K * N;
    float* Tol = To + (size_t)blockIdx.z * lso;
    int n0 = blockIdx.x * 32, k0 = blockIdx.y * 32;
    int tx = threadIdx.x & 31, ty = threadIdx.x >> 5;
    #pragma unroll
    for (int i = 0; i < 4; i++)
        tile[ty + i * 8][tx] = Wl[(size_t)(k0 + ty + i * 8) * N + n0 + tx];
    __syncthreads();
    #pragma unroll
    for (int i = 0; i < 4; i++) {
        int n = n0 + ty + i * 8;
        int k = k0 + tx;
        Tol[(size_t)n * K + k] = tf32r(tile[tx][ty + i * 8]);
    }
}

// ================= tf32 mma.sync GEMM, 3-stage cp.async pipeline =================
#define STP 128
#define STT (128 * STP)
#define STB (2 * STT)
#define GSM (3 * STB)

template<int RELU, int WF32, int WROUND>
__global__ __launch_bounds__(256, 1)
void tf32_gemm_kernel(const float* __restrict__ A, const float* __restrict__ Bt,
                      const float* __restrict__ bias,
                      float* __restrict__ Cf, float* __restrict__ Cr,
                      int M, int N, int K) {
    extern __shared__ char smem_raw[];
    uint32_t sb = smem_u32(smem_raw);

    int tid = threadIdx.x, wid = tid >> 5, lane = tid & 31;
    int g = lane >> 2, tq = lane & 3;
    int wm = (wid >> 2) * 64;
    int wn = (wid & 3) * 32;
    int bm = blockIdx.y * 128, bn = blockIdx.x * 128;

    const float* baseA = A  + (size_t)bm * K;
    const float* baseB = Bt + (size_t)bn * K;
    int nch = K / 32;

    auto load_chunk = [&](int ci, int s) {
        uint32_t st = sb + s * STB;
        int k0 = ci * 32;
        #pragma unroll
        for (int j = 0; j < 8; j++) {
            int seg  = tid + j * 256;
            int tens = seg >> 10;
            int rem  = seg & 1023;
            int row  = rem >> 3;
            int c    = rem & 7;
            uint32_t dst = st + tens * STT + row * STP + ((c ^ (row & 7)) << 4);
            const float* src = (tens ? baseB : baseA) + (size_t)row * K + k0 + c * 4;
            cpa16(dst, src);
        }
        asm volatile("cp.async.commit_group;" ::: "memory");
    };

    float acc[4][4][4];
    #pragma unroll
    for (int a = 0; a < 4; a++)
        #pragma unroll
        for (int b = 0; b < 4; b++)
            #pragma unroll
            for (int c = 0; c < 4; c++) acc[a][b][c] = 0.f;

    load_chunk(0, 0);
    load_chunk(1, 1);
    load_chunk(2, 2);

    int arow_l = (lane & 7) + ((lane >> 3) & 1) * 8;
    int acb    = (lane >> 4);
    int brow_l = (lane & 7) + ((lane >> 4) << 3);
    int bcb    = (lane >> 3) & 1;

    for (int i = 0; i < nch; i++) {
        int rem = nch - 1 - i;
        if (rem >= 2)      asm volatile("cp.async.wait_group 2;" ::: "memory");
        else if (rem == 1) asm volatile("cp.async.wait_group 1;" ::: "memory");
        else               asm volatile("cp.async.wait_group 0;" ::: "memory");
        __syncthreads();

        uint32_t stA = sb + (i % 3) * STB;
        uint32_t stB = stA + STT;

        #pragma unroll
        for (int kk = 0; kk < 4; kk++) {
            uint32_t af[4][4], bf[2][4];
            #pragma unroll
            for (int mi = 0; mi < 4; mi++) {
                int r = wm + mi * 16 + arow_l;
                int c = kk * 2 + acb;
                ldsm4(af[mi], stA + r * STP + ((c ^ (r & 7)) << 4));
            }
            #pragma unroll
            for (int nb = 0; nb < 2; nb++) {
                int r = wn + nb * 16 + brow_l;
                int c = kk * 2 + bcb;
                ldsm4(bf[nb], stB + r * STP + ((c ^ (r & 7)) << 4));
            }
            #pragma unroll
            for (int mi = 0; mi < 4; mi++)
                #pragma unroll
                for (int ni = 0; ni < 4; ni++) {
                    int nb = ni >> 1, o = (ni & 1) * 2;
                    mma_tf32(acc[mi][ni], af[mi], bf[nb][o], bf[nb][o + 1]);
                }
        }
        __syncthreads();
        if (i + 3 < nch) load_chunk(i + 3, i % 3);
    }

    #pragma unroll
    for (int mi = 0; mi < 4; mi++) {
        int r0 = bm + wm + mi * 16 + g;
        #pragma unroll
        for (int ni = 0; ni < 4; ni++) {
            int c0 = bn + wn + ni * 8 + 2 * tq;
            float bx = bias[c0], by = bias[c0 + 1];
            float2 v0, v1;
            v0.x = acc[mi][ni][0] + bx; v0.y = acc[mi][ni][1] + by;
            v1.x = acc[mi][ni][2] + bx; v1.y = acc[mi][ni][3] + by;
            if (RELU) {
                v0.x = fmaxf(v0.x, 0.f); v0.y = fmaxf(v0.y, 0.f);
                v1.x = fmaxf(v1.x, 0.f); v1.y = fmaxf(v1.y, 0.f);
            }
            if (WF32) {
                *(float2*)(Cf + (size_t)r0 * N + c0)       = v0;
                *(float2*)(Cf + (size_t)(r0 + 8) * N + c0) = v1;
            }
            if (WROUND) {
                float2 w0, w1;
                w0.x = tf32r(v0.x); w0.y = tf32r(v0.y);
                w1.x = tf32r(v1.x); w1.y = tf32r(v1.y);
                *(float2*)(Cr + (size_t)r0 * N + c0)       = w0;
                *(float2*)(Cr + (size_t)(r0 + 8) * N + c0) = w1;
            }
        }
    }
}

// ================= fused flash attention (tf32 mma) =================
// grid (16, B*H), block 128. Each block: one 64-row Q tile of one head.
// qkv buffer is tf32-rounded. Output: tf32-rounded attn into xr.
#define FP 68                                 // smem row pitch (floats)
#define FTILE (64 * FP)                       // floats per tile region
#define FSMEM (4 * FTILE * 4)                 // bytes: QVs, Ks, Vt, Ps

__global__ __launch_bounds__(128)
void flash_kernel(const float* __restrict__ qkv, float* __restrict__ xr) {
    extern __shared__ float fs[];
    float* QVs = fs;                 // Q tile, later V staging
    float* Ks  = fs + FTILE;
    float* Vt  = fs + 2 * FTILE;     // V transposed [d][j]
    float* Ps  = fs + 3 * FTILE;
    uint32_t sbQ = smem_u32(QVs), sbK = smem_u32(Ks), sbP = smem_u32(Ps);

    int it = (int)gridDim.x - 1 - (int)blockIdx.x;   // longest first
    int bh = blockIdx.y;
    int b = bh >> 4, h = bh & 15;
    int tid = threadIdx.x, wid = tid >> 5, lane = tid & 31;
    int g = lane >> 2, tq = lane & 3;
    int wm = wid * 16;

    int arow = (lane & 7) + ((lane >> 3) & 1) * 8;
    int acb  = lane >> 4;
    int brow = (lane & 7) + ((lane >> 4) << 3);
    int bcb  = (lane >> 3) & 1;

    // ---- load Q tile ----
    const float* qbase = qkv + (size_t)(b * T_ + it * 64) * E3 + h * HD;
    #pragma unroll
    for (int p = 0; p < 8; p++) {
        int seg = tid + p * 128;
        int r = seg >> 4, c = seg & 15;
        cpa16(sbQ + (uint32_t)(r * FP + c * 4) * 4, qbase + (size_t)r * E3 + c * 4);
    }
    asm volatile("cp.async.commit_group;" ::: "memory");
    asm volatile("cp.async.wait_group 0;" ::: "memory");
    __syncthreads();

    uint32_t qf[8][4];
    #pragma unroll
    for (int kk = 0; kk < 8; kk++) {
        int c = kk * 2 + acb;
        ldsm4(qf[kk], sbQ + (uint32_t)((wm + arow) * FP + c * 4) * 4);
    }
    __syncthreads();     // QVs now reusable as V staging

    float m0 = -1e30f, m1 = -1e30f, l0 = 0.f, l1 = 0.f;
    float oac[8][4];
    #pragma unroll
    for (int n = 0; n < 8; n++)
        #pragma unroll
        for (int c = 0; c < 4; c++) oac[n][c] = 0.f;

    const float* kbase = qkv + (size_t)(b * T_) * E3 + E_     + h * HD;
    const float* vbase = qkv + (size_t)(b * T_) * E3 + 2 * E_ + h * HD;

    for (int jt = 0; jt <= it; jt++) {
        // ---- load K, V tiles ----
        const float* kb = kbase + (size_t)jt * 64 * E3;
        const float* vb = vbase + (size_t)jt * 64 * E3;
        #pragma unroll
        for (int p = 0; p < 8; p++) {
            int seg = tid + p * 128;
            int r = seg >> 4, c = seg & 15;
            cpa16(sbK + (uint32_t)(r * FP + c * 4) * 4, kb + (size_t)r * E3 + c * 4);
            cpa16(sbQ + (uint32_t)(r * FP + c * 4) * 4, vb + (size_t)r * E3 + c * 4);
        }
        asm volatile("cp.async.commit_group;" ::: "memory");
        asm volatile("cp.async.wait_group 0;" ::: "memory");
        __syncthreads();

        // ---- S = Q K^T ----
        float sac[8][4];
        #pragma unroll
        for (int n = 0; n < 8; n++)
            #pragma unroll
            for (int c = 0; c < 4; c++) sac[n][c] = 0.f;
        #pragma unroll
        for (int kk = 0; kk < 8; kk++) {
            uint32_t bf[4][4];
            #pragma unroll
            for (int nb = 0; nb < 4; nb++) {
                int c = kk * 2 + bcb;
                ldsm4(bf[nb], sbK + (uint32_t)((nb * 16 + brow) * FP + c * 4) * 4);
            }
            #pragma unroll
            for (int ni = 0; ni < 8; ni++) {
                int nb = ni >> 1, o = (ni & 1) * 2;
                mma_tf32(sac[ni], qf[kk], bf[nb][o], bf[nb][o + 1]);
            }
        }

        // ---- transpose V (QVs[j][d] -> Vt[d][j]), conflict-free ----
        #pragma unroll
        for (int p = 0; p < 8; p++) {
            int seg = tid + p * 128;
            int j = seg & 63, dc = seg >> 6;
            float4 v = *(float4*)&QVs[j * FP + dc * 4];
            Vt[(dc * 4 + 0) * FP + j] = v.x;
            Vt[(dc * 4 + 1) * FP + j] = v.y;
            Vt[(dc * 4 + 2) * FP + j] = v.z;
            Vt[(dc * 4 + 3) * FP + j] = v.w;
        }
        __syncthreads();

        // ---- online softmax on fragments ----
        #pragma unroll
        for (int ni = 0; ni < 8; ni++) {
            sac[ni][0] *= 0.125f; sac[ni][1] *= 0.125f;
            sac[ni][2] *= 0.125f; sac[ni][3] *= 0.125f;
        }
        if (jt == it) {
            #pragma unroll
            for (int ni = 0; ni < 8; ni++) {
                int cb = ni * 8 + 2 * tq;
                int r0 = wm + g, r1 = wm + g + 8;
                if (cb     > r0) sac[ni][0] = -1e30f;
                if (cb + 1 > r0) sac[ni][1] = -1e30f;
                if (cb     > r1) sac[ni][2] = -1e30f;
                if (cb + 1 > r1) sac[ni][3] = -1e30f;
            }
        }
        float a0 = -1e30f, a1 = -1e30f;
        #pragma unroll
        for (int ni = 0; ni < 8; ni++) {
            a0 = fmaxf(a0, fmaxf(sac[ni][0], sac[ni][1]));
            a1 = fmaxf(a1, fmaxf(sac[ni][2], sac[ni][3]));
        }
        a0 = fmaxf(a0, __shfl_xor_sync(0xffffffffu, a0, 1));
        a0 = fmaxf(a0, __shfl_xor_sync(0xffffffffu, a0, 2));
        a1 = fmaxf(a1, __shfl_xor_sync(0xffffffffu, a1, 1));
        a1 = fmaxf(a1, __shfl_xor_sync(0xffffffffu, a1, 2));
        float mn0 = fmaxf(m0, a0), mn1 = fmaxf(m1, a1);
        float al0 = __expf(m0 - mn0), al1 = __expf(m1 - mn1);
        m0 = mn0; m1 = mn1;
        l0 *= al0; l1 *= al1;
        #pragma unroll
        for (int ni = 0; ni < 8; ni++) {
            oac[ni][0] *= al0; oac[ni][1] *= al0;
            oac[ni][2] *= al1; oac[ni][3] *= al1;
        }
        float s0 = 0.f, s1 = 0.f;
        #pragma unroll
        for (int ni = 0; ni < 8; ni++) {
            float p0 = tf32r(__expf(sac[ni][0] - mn0));
            float p1 = tf32r(__expf(sac[ni][1] - mn0));
            float p2 = tf32r(__expf(sac[ni][2] - mn1));
            float p3 = tf32r(__expf(sac[ni][3] - mn1));
            s0 += p0 + p1; s1 += p2 + p3;
            int cb = ni * 8 + 2 * tq;
            float2 w0 = {p0, p1}, w1 = {p2, p3};
            *(float2*)&Ps[(wm + g) * FP + cb]     = w0;
            *(float2*)&Ps[(wm + g + 8) * FP + cb] = w1;
        }
        s0 += __shfl_xor_sync(0xffffffffu, s0, 1);
        s0 += __shfl_xor_sync(0xffffffffu, s0, 2);
        s1 += __shfl_xor_sync(0xffffffffu, s1, 1);
        s1 += __shfl_xor_sync(0xffffffffu, s1, 2);
        l0 += s0; l1 += s1;
        __syncwarp();

        // ---- O += P V ----
        #pragma unroll
        for (int kk = 0; kk < 8; kk++) {
            uint32_t pf[4];
            int c = kk * 2 + acb;
            ldsm4(pf, sbP + (uint32_t)((wm + arow) * FP + c * 4) * 4);
            #pragma unroll
            for (int nd = 0; nd < 8; nd++) {
                uint32_t b0 = __float_as_uint(Vt[(nd * 8 + g) * FP + kk * 8 + tq]);
                uint32_t b1 = __float_as_uint(Vt[(nd * 8 + g) * FP + kk * 8 + tq + 4]);
                mma_tf32(oac[nd], pf, b0, b1);
            }
        }
        __syncthreads();
    }

    // ---- write O (tf32-rounded) ----
    float inv0 = 1.f / l0, inv1 = 1.f / l1;
    float* od = xr + (size_t)(b * T_ + it * 64 + wm + g) * E_ + h * HD;
    #pragma unroll
    for (int nd = 0; nd < 8; nd++) {
        int cb = nd * 8 + 2 * tq;
        float2 v0, v1;
        v0.x = tf32r(oac[nd][0] * inv0); v0.y = tf32r(oac[nd][1] * inv0);
        v1.x = tf32r(oac[nd][2] * inv1); v1.y = tf32r(oac[nd][3] * inv1);
        *(float2*)(od + cb)               = v0;
        *(float2*)(od + (size_t)8 * E_ + cb) = v1;
    }
}

// ---------------- out = LayerNorm(in (+ res)) ----------------
__global__ void add_ln_kernel(const float* __restrict__ in,
                              const float* __restrict__ res,
                              const float* __restrict__ g,
                              const float* __restrict__ bb,
                              float* __restrict__ out,
                              float* __restrict__ outr) {
    int row = blockIdx.x;
    int t = threadIdx.x;
    float4 v = ((const float4*)(in + (size_t)row * E_))[t];
    if (res) {
        float4 r = ((const float4*)(res + (size_t)row * E_))[t];
        v.x += r.x; v.y += r.y; v.z += r.z; v.w += r.w;
    }
    float s  = v.x + v.y + v.z + v.w;
    float s2 = v.x * v.x + v.y * v.y + v.z * v.z + v.w * v.w;

    __shared__ float sh[16];
    s = warpSum(s); s2 = warpSum(s2);
    int w = t >> 5, lane = t & 31;
    if (lane == 0) { sh[w] = s; sh[w + 8] = s2; }
    __syncthreads();
    if (w == 0) {
        float a  = (lane < 8) ? sh[lane] : 0.f;
        a = warpSum(a);
        float a2 = (lane < 8) ? sh[lane + 8] : 0.f;
        a2 = warpSum(a2);
        if (lane == 0) { sh[0] = a; sh[8] = a2; }
    }
    __syncthreads();
    float mean = sh[0] * (1.f / E_);
    float var  = sh[8] * (1.f / E_) - mean * mean;
    float rstd = rsqrtf(var + 1e-5f);

    float4 gv = ((const float4*)g)[t];
    float4 bv = ((const float4*)bb)[t];
    float4 o;
    o.x = (v.x - mean) * rstd * gv.x + bv.x;
    o.y = (v.y - mean) * rstd * gv.y + bv.y;
    o.z = (v.z - mean) * rstd * gv.z + bv.z;
    o.w = (v.w - mean) * rstd * gv.w + bv.w;
    ((float4*)(out + (size_t)row * E_))[t] = o;

    float4 r;
    r.x = tf32r(o.x); r.y = tf32r(o.y); r.z = tf32r(o.z); r.w = tf32r(o.w);
    ((float4*)(outr + (size_t)row * E_))[t] = r;
}

// ---------------- host launch ----------------
extern "C" void kernel_launch(void* const* d_in, const int* in_sizes, int n_in,
                              void* d_out, int out_size) {
    const int*   idx   = (const int*)  d_in[0];
    const float* tok   = (const float*)d_in[1];
    const float* pos   = (const float*)d_in[2];
    const float* Wq    = (const float*)d_in[3];
    const float* bq    = (const float*)d_in[4];
    const float* Wk    = (const float*)d_in[5];
    const float* bk    = (const float*)d_in[6];
    const float* Wv    = (const float*)d_in[7];
    const float* bv    = (const float*)d_in[8];
    const float* Wo    = (const float*)d_in[9];
    const float* bo    = (const float*)d_in[10];
    const float* W1    = (const float*)d_in[11];
    const float* b1    = (const float*)d_in[12];
    const float* W2    = (const float*)d_in[13];
    const float* b2    = (const float*)d_in[14];
    const float* ln1g  = (const float*)d_in[15];
    const float* ln1b  = (const float*)d_in[16];
    const float* ln2g  = (const float*)d_in[17];
    const float* ln2b  = (const float*)d_in[18];
    const float* lnfg  = (const float*)d_in[19];
    const float* lnfb  = (const float*)d_in[20];
    const float* Whead = (const float*)d_in[21];
    const float* bhead = (const float*)d_in[22];
    float* out = (float*)d_out;

    float *x, *xr, *qkv, *tmp, *ffr, *bqkv, *wt;
    cudaGetSymbolAddress((void**)&x,    g_x);
    cudaGetSymbolAddress((void**)&xr,   g_xr);
    cudaGetSymbolAddress((void**)&qkv,  g_qkv);
    cudaGetSymbolAddress((void**)&tmp,  g_tmp);
    cudaGetSymbolAddress((void**)&ffr,  g_ffr);
    cudaGetSymbolAddress((void**)&bqkv, g_bqkv);
    cudaGetSymbolAddress((void**)&wt,   g_wt);

    cudaFuncSetAttribute(tf32_gemm_kernel<0,1,0>,
                         cudaFuncAttributeMaxDynamicSharedMemorySize, GSM);
    cudaFuncSetAttribute(tf32_gemm_kernel<1,0,1>,
                         cudaFuncAttributeMaxDynamicSharedMemorySize, GSM);
    cudaFuncSetAttribute(tf32_gemm_kernel<0,0,1>,
                         cudaFuncAttributeMaxDynamicSharedMemorySize, GSM);
    cudaFuncSetAttribute(flash_kernel,
                         cudaFuncAttributeMaxDynamicSharedMemorySize, FSMEM);

    tconv_kernel<<<dim3(E_ / 32,  E_ / 32,  L_), 256>>>(Wq, wt + OQKV,             E_, E_, 3 * SZ_EE);
    tconv_kernel<<<dim3(E_ / 32,  E_ / 32,  L_), 256>>>(Wk, wt + OQKV + SZ_EE,     E_, E_, 3 * SZ_EE);
    tconv_kernel<<<dim3(E_ / 32,  E_ / 32,  L_), 256>>>(Wv, wt + OQKV + 2 * SZ_EE, E_, E_, 3 * SZ_EE);
    tconv_kernel<<<dim3(E_ / 32,  E_ / 32,  L_), 256>>>(Wo, wt + OWO,  E_,  E_,  SZ_EE);
    tconv_kernel<<<dim3(FF_ / 32, E_ / 32,  L_), 256>>>(W1, wt + OW1,  E_,  FF_, (size_t)E_ * FF_);
    tconv_kernel<<<dim3(E_ / 32,  FF_ / 32, L_), 256>>>(W2, wt + OW2,  FF_, E_,  (size_t)E_ * FF_);
    tconv_kernel<<<dim3(V_ / 32,  E_ / 32,  1 ), 256>>>(Whead, wt + OHEAD, E_, V_, 0);
    pack_bias_kernel<<<dim3(12, L_), 256>>>(bq, bk, bv, bqkv);

    embed_kernel<<<BT, 256>>>(idx, tok, pos, x, xr);

    dim3 gQKV(E3 / 128, BT / 128);
    dim3 gEE(E_ / 128, BT / 128);
    dim3 gEF(FF_ / 128, BT / 128);
    dim3 gHead(V_ / 128, BT / 128);

    for (int l = 0; l < L_; l++) {
        tf32_gemm_kernel<0,0,1><<<gQKV, 256, GSM>>>(
            xr, wt + OQKV + (size_t)l * 3 * SZ_EE, bqkv + l * E3,
            nullptr, qkv, BT, E3, E_);

        flash_kernel<<<dim3(16, B_ * H_), 128, FSMEM>>>(qkv, xr);

        tf32_gemm_kernel<0,1,0><<<gEE, 256, GSM>>>(
            xr, wt + OWO + (size_t)l * SZ_EE, bo + l * E_,
            tmp, nullptr, BT, E_, E_);
        add_ln_kernel<<<BT, 256>>>(x, tmp, ln1g + l * E_, ln1b + l * E_, x, xr);

        tf32_gemm_kernel<1,0,1><<<gEF, 256, GSM>>>(
            xr, wt + OW1 + (size_t)l * E_ * FF_, b1 + l * FF_,
            nullptr, ffr, BT, FF_, E_);
        tf32_gemm_kernel<0,1,0><<<gEE, 256, GSM>>>(
            ffr, wt + OW2 + (size_t)l * E_ * FF_, b2 + l * E_,
            tmp, nullptr, BT, E_, FF_);
        add_ln_kernel<<<BT, 256>>>(x, tmp, ln2g + l * E_, ln2b + l * E_, x, xr);
    }

    add_ln_kernel<<<BT, 256>>>(x, nullptr, lnfg, lnfb, x, xr);
    tf32_gemm_kernel<0,1,0><<<gHead, 256, GSM>>>(
        xr, wt + OHEAD, bhead, out, nullptr, BT, V_, E_);
}

// round 9
// speedup vs baseline: 6.0519x; 1.6818x over previous
#include <cuda_runtime.h>
#include <cuda_fp16.h>
#include <math.h>
#include <stdint.h>

#define B_  4
#define T_  1024
#define E_  1024
#define H_  16
#define HD  64
#define L_  6
#define FF_ 4096
#define V_  32000
#define BT  (B_ * T_)
#define E3  (3 * E_)

#define SZ_EE ((size_t)E_ * E_)
#define OQKV  ((size_t)0)
#define OWO   ((size_t)18 * SZ_EE)
#define OW1   ((size_t)24 * SZ_EE)
#define OW2   ((size_t)48 * SZ_EE)
#define OHEAD ((size_t)72 * SZ_EE)
#define WTOT  (OHEAD + (size_t)E_ * V_)

// ---------------- device scratch ----------------
__device__ float  g_x[BT * E_];
__device__ __half g_xr[BT * E_];             // fp16 GEMM input (LN out / attn out)
__device__ float  g_qkv[(size_t)BT * E3];    // tf32-rounded QKV (flash input)
__device__ float  g_tmp[BT * E_];
__device__ __half g_ffr[(size_t)BT * FF_];
__device__ float  g_bqkv[L_ * E3];
__device__ __half g_wt[WTOT];                // fp16 transposed weights

// ---------------- helpers ----------------
__device__ __forceinline__ uint32_t smem_u32(const void* p) {
    uint32_t a;
    asm("{ .reg .u64 t; cvta.to.shared.u64 t, %1; cvt.u32.u64 %0, t; }" : "=r"(a) : "l"(p));
    return a;
}
__device__ __forceinline__ float warpSum(float v) {
    #pragma unroll
    for (int o = 16; o > 0; o >>= 1) v += __shfl_xor_sync(0xffffffffu, v, o);
    return v;
}
__device__ __forceinline__ float tf32r(float x) {
    float y;
    asm("cvt.rna.tf32.f32 %0, %1;" : "=f"(y) : "f"(x));
    return y;
}
__device__ __forceinline__ void ldsm4(uint32_t* r, uint32_t addr) {
    asm volatile("ldmatrix.sync.aligned.m8n8.x4.shared.b16 {%0,%1,%2,%3}, [%4];"
                 : "=r"(r[0]), "=r"(r[1]), "=r"(r[2]), "=r"(r[3]) : "r"(addr));
}
__device__ __forceinline__ void cpa16(uint32_t dst, const void* src) {
    asm volatile("cp.async.cg.shared.global [%0], [%1], 16;" :: "r"(dst), "l"(src));
}
__device__ __forceinline__ void mma_f16(float* c, const uint32_t* a, uint32_t b0, uint32_t b1) {
    asm volatile(
        "mma.sync.aligned.m16n8k16.row.col.f32.f16.f16.f32 "
        "{%0,%1,%2,%3}, {%4,%5,%6,%7}, {%8,%9}, {%0,%1,%2,%3};\n"
        : "+f"(c[0]), "+f"(c[1]), "+f"(c[2]), "+f"(c[3])
        : "r"(a[0]), "r"(a[1]), "r"(a[2]), "r"(a[3]), "r"(b0), "r"(b1));
}
__device__ __forceinline__ void mma_tf32(float* c, const uint32_t* a, uint32_t b0, uint32_t b1) {
    asm volatile(
        "mma.sync.aligned.m16n8k8.row.col.f32.tf32.tf32.f32 "
        "{%0,%1,%2,%3}, {%4,%5,%6,%7}, {%8,%9}, {%0,%1,%2,%3};\n"
        : "+f"(c[0]), "+f"(c[1]), "+f"(c[2]), "+f"(c[3])
        : "r"(a[0]), "r"(a[1]), "r"(a[2]), "r"(a[3]), "r"(b0), "r"(b1));
}

// ---------------- embedding ----------------
__global__ void embed_kernel(const int* __restrict__ idx,
                             const float* __restrict__ tok,
                             const float* __restrict__ pos,
                             float* __restrict__ x,
                             __half* __restrict__ xr) {
    int bt = blockIdx.x;
    int t  = bt & (T_ - 1);
    int id = idx[bt];
    int c  = threadIdx.x;
    float4 a = ((const float4*)(tok + (size_t)id * E_))[c];
    float4 p = ((const float4*)(pos + (size_t)t  * E_))[c];
    a.x += p.x; a.y += p.y; a.z += p.z; a.w += p.w;
    ((float4*)(x + (size_t)bt * E_))[c] = a;
    __half2 h0 = __floats2half2_rn(a.x, a.y);
    __half2 h1 = __floats2half2_rn(a.z, a.w);
    uint2 u; u.x = *(uint32_t*)&h0; u.y = *(uint32_t*)&h1;
    ((uint2*)(xr + (size_t)bt * E_))[c] = u;
}

// ---------------- bias pack for fused QKV ----------------
__global__ void pack_bias_kernel(const float* __restrict__ bq,
                                 const float* __restrict__ bk,
                                 const float* __restrict__ bv,
                                 float* __restrict__ o) {
    int l = blockIdx.y;
    int i = blockIdx.x * 256 + threadIdx.x;
    int w = i >> 10, c = i & 1023;
    const float* s = (w == 0) ? bq : (w == 1) ? bk : bv;
    o[l * E3 + i] = s[l * E_ + c];
}

// ---------------- weight transpose + fp16 round ----------------
__global__ void tconv_kernel(const float* __restrict__ W,
                             __half* __restrict__ To,
                             int K, int N, size_t lso) {
    __shared__ float tile[32][33];
    const float* Wl = W + (size_t)blockIdx.z * K * N;
    __half* Tol = To + (size_t)blockIdx.z * lso;
    int n0 = blockIdx.x * 32, k0 = blockIdx.y * 32;
    int tx = threadIdx.x & 31, ty = threadIdx.x >> 5;
    #pragma unroll
    for (int i = 0; i < 4; i++)
        tile[ty + i * 8][tx] = Wl[(size_t)(k0 + ty + i * 8) * N + n0 + tx];
    __syncthreads();
    #pragma unroll
    for (int i = 0; i < 4; i++) {
        int n = n0 + ty + i * 8;
        int k = k0 + tx;
        Tol[(size_t)n * K + k] = __float2half_rn(tile[tx][ty + i * 8]);
    }
}

// ================= fp16 mma.sync GEMM, 3-stage cp.async pipeline =================
// C = A[M,K] * (Bt[N,K])^T + bias. A/Bt fp16. CTA 128x128, K-chunk 64 (128B/row).
// MODE: 0 = fp32 out, 1 = tf32-rounded fp32 out, 2 = fp16 out.
#define STP 128
#define STT (128 * STP)
#define STB (2 * STT)
#define GSM (3 * STB)

template<int RELU, int MODE>
__global__ __launch_bounds__(256, 1)
void h16_gemm_kernel(const __half* __restrict__ A, const __half* __restrict__ Bt,
                     const float* __restrict__ bias,
                     float* __restrict__ Cf, __half* __restrict__ Ch,
                     int M, int N, int K) {
    extern __shared__ char smem_raw[];
    uint32_t sb = smem_u32(smem_raw);

    int tid = threadIdx.x, wid = tid >> 5, lane = tid & 31;
    int g = lane >> 2, tq = lane & 3;
    int wm = (wid >> 2) * 64;
    int wn = (wid & 3) * 32;
    int bm = blockIdx.y * 128, bn = blockIdx.x * 128;

    const __half* baseA = A  + (size_t)bm * K;
    const __half* baseB = Bt + (size_t)bn * K;
    int nch = K / 64;

    auto load_chunk = [&](int ci, int s) {
        uint32_t st = sb + s * STB;
        int k0 = ci * 64;
        #pragma unroll
        for (int j = 0; j < 8; j++) {
            int seg  = tid + j * 256;
            int tens = seg >> 10;
            int rem  = seg & 1023;
            int row  = rem >> 3;
            int c    = rem & 7;
            uint32_t dst = st + tens * STT + row * STP + ((c ^ (row & 7)) << 4);
            const __half* src = (tens ? baseB : baseA) + (size_t)row * K + k0 + c * 8;
            cpa16(dst, src);
        }
        asm volatile("cp.async.commit_group;" ::: "memory");
    };

    float acc[4][4][4];
    #pragma unroll
    for (int a = 0; a < 4; a++)
        #pragma unroll
        for (int b = 0; b < 4; b++)
            #pragma unroll
            for (int c = 0; c < 4; c++) acc[a][b][c] = 0.f;

    load_chunk(0, 0);
    load_chunk(1, 1);
    load_chunk(2, 2);

    int arow_l = lane & 15;
    int acb    = lane >> 4;
    int brow_l = (lane & 7) + ((lane >> 4) << 3);
    int bcb    = (lane >> 3) & 1;

    for (int i = 0; i < nch; i++) {
        int rem = nch - 1 - i;
        if (rem >= 2)      asm volatile("cp.async.wait_group 2;" ::: "memory");
        else if (rem == 1) asm volatile("cp.async.wait_group 1;" ::: "memory");
        else               asm volatile("cp.async.wait_group 0;" ::: "memory");
        __syncthreads();

        uint32_t stA = sb + (i % 3) * STB;
        uint32_t stB = stA + STT;

        #pragma unroll
        for (int kk = 0; kk < 4; kk++) {      // 4 k16 steps per K=64 chunk
            uint32_t af[4][4], bf[2][4];
            #pragma unroll
            for (int mi = 0; mi < 4; mi++) {
                int r = wm + mi * 16 + arow_l;
                int c = kk * 2 + acb;
                ldsm4(af[mi], stA + r * STP + ((c ^ (r & 7)) << 4));
            }
            #pragma unroll
            for (int nb = 0; nb < 2; nb++) {
                int r = wn + nb * 16 + brow_l;
                int c = kk * 2 + bcb;
                ldsm4(bf[nb], stB + r * STP + ((c ^ (r & 7)) << 4));
            }
            #pragma unroll
            for (int mi = 0; mi < 4; mi++)
                #pragma unroll
                for (int ni = 0; ni < 4; ni++) {
                    int nb = ni >> 1, o = (ni & 1) * 2;
                    mma_f16(acc[mi][ni], af[mi], bf[nb][o], bf[nb][o + 1]);
                }
        }
        __syncthreads();
        if (i + 3 < nch) load_chunk(i + 3, i % 3);
    }

    #pragma unroll
    for (int mi = 0; mi < 4; mi++) {
        int r0 = bm + wm + mi * 16 + g;
        #pragma unroll
        for (int ni = 0; ni < 4; ni++) {
            int c0 = bn + wn + ni * 8 + 2 * tq;
            float bx = bias[c0], by = bias[c0 + 1];
            float2 v0, v1;
            v0.x = acc[mi][ni][0] + bx; v0.y = acc[mi][ni][1] + by;
            v1.x = acc[mi][ni][2] + bx; v1.y = acc[mi][ni][3] + by;
            if (RELU) {
                v0.x = fmaxf(v0.x, 0.f); v0.y = fmaxf(v0.y, 0.f);
                v1.x = fmaxf(v1.x, 0.f); v1.y = fmaxf(v1.y, 0.f);
            }
            if (MODE == 0) {
                *(float2*)(Cf + (size_t)r0 * N + c0)       = v0;
                *(float2*)(Cf + (size_t)(r0 + 8) * N + c0) = v1;
            } else if (MODE == 1) {
                float2 w0, w1;
                w0.x = tf32r(v0.x); w0.y = tf32r(v0.y);
                w1.x = tf32r(v1.x); w1.y = tf32r(v1.y);
                *(float2*)(Cf + (size_t)r0 * N + c0)       = w0;
                *(float2*)(Cf + (size_t)(r0 + 8) * N + c0) = w1;
            } else {
                __half2 h0 = __floats2half2_rn(v0.x, v0.y);
                __half2 h1 = __floats2half2_rn(v1.x, v1.y);
                *(__half2*)(Ch + (size_t)r0 * N + c0)       = h0;
                *(__half2*)(Ch + (size_t)(r0 + 8) * N + c0) = h1;
            }
        }
    }
}

// ================= fused flash attention (tf32 mma) =================
// grid (16, B*H), block 128. qkv fp32 tf32-rounded. Output fp16 into xr.
#define FP 68
#define FTILE (64 * FP)
#define FSMEM (4 * FTILE * 4)

__global__ __launch_bounds__(128)
void flash_kernel(const float* __restrict__ qkv, __half* __restrict__ xr) {
    extern __shared__ float fs[];
    float* QVs = fs;
    float* Ks  = fs + FTILE;
    float* Vt  = fs + 2 * FTILE;
    float* Ps  = fs + 3 * FTILE;
    uint32_t sbQ = smem_u32(QVs), sbK = smem_u32(Ks), sbP = smem_u32(Ps);

    int it = (int)gridDim.x - 1 - (int)blockIdx.x;
    int bh = blockIdx.y;
    int b = bh >> 4, h = bh & 15;
    int tid = threadIdx.x, wid = tid >> 5, lane = tid & 31;
    int g = lane >> 2, tq = lane & 3;
    int wm = wid * 16;

    int arow = (lane & 7) + ((lane >> 3) & 1) * 8;
    int acb  = lane >> 4;
    int brow = (lane & 7) + ((lane >> 4) << 3);
    int bcb  = (lane >> 3) & 1;

    const float* qbase = qkv + (size_t)(b * T_ + it * 64) * E3 + h * HD;
    #pragma unroll
    for (int p = 0; p < 8; p++) {
        int seg = tid + p * 128;
        int r = seg >> 4, c = seg & 15;
        cpa16(sbQ + (uint32_t)(r * FP + c * 4) * 4, qbase + (size_t)r * E3 + c * 4);
    }
    asm volatile("cp.async.commit_group;" ::: "memory");
    asm volatile("cp.async.wait_group 0;" ::: "memory");
    __syncthreads();

    uint32_t qf[8][4];
    #pragma unroll
    for (int kk = 0; kk < 8; kk++) {
        int c = kk * 2 + acb;
        ldsm4(qf[kk], sbQ + (uint32_t)((wm + arow) * FP + c * 4) * 4);
    }
    __syncthreads();

    float m0 = -1e30f, m1 = -1e30f, l0 = 0.f, l1 = 0.f;
    float oac[8][4];
    #pragma unroll
    for (int n = 0; n < 8; n++)
        #pragma unroll
        for (int c = 0; c < 4; c++) oac[n][c] = 0.f;

    const float* kbase = qkv + (size_t)(b * T_) * E3 + E_     + h * HD;
    const float* vbase = qkv + (size_t)(b * T_) * E3 + 2 * E_ + h * HD;

    for (int jt = 0; jt <= it; jt++) {
        const float* kb = kbase + (size_t)jt * 64 * E3;
        const float* vb = vbase + (size_t)jt * 64 * E3;
        #pragma unroll
        for (int p = 0; p < 8; p++) {
            int seg = tid + p * 128;
            int r = seg >> 4, c = seg & 15;
            cpa16(sbK + (uint32_t)(r * FP + c * 4) * 4, kb + (size_t)r * E3 + c * 4);
            cpa16(sbQ + (uint32_t)(r * FP + c * 4) * 4, vb + (size_t)r * E3 + c * 4);
        }
        asm volatile("cp.async.commit_group;" ::: "memory");
        asm volatile("cp.async.wait_group 0;" ::: "memory");
        __syncthreads();

        float sac[8][4];
        #pragma unroll
        for (int n = 0; n < 8; n++)
            #pragma unroll
            for (int c = 0; c < 4; c++) sac[n][c] = 0.f;
        #pragma unroll
        for (int kk = 0; kk < 8; kk++) {
            uint32_t bf[4][4];
            #pragma unroll
            for (int nb = 0; nb < 4; nb++) {
                int c = kk * 2 + bcb;
                ldsm4(bf[nb], sbK + (uint32_t)((nb * 16 + brow) * FP + c * 4) * 4);
            }
            #pragma unroll
            for (int ni = 0; ni < 8; ni++) {
                int nb = ni >> 1, o = (ni & 1) * 2;
                mma_tf32(sac[ni], qf[kk], bf[nb][o], bf[nb][o + 1]);
            }
        }

        #pragma unroll
        for (int p = 0; p < 8; p++) {
            int seg = tid + p * 128;
            int j = seg & 63, dc = seg >> 6;
            float4 v = *(float4*)&QVs[j * FP + dc * 4];
            Vt[(dc * 4 + 0) * FP + j] = v.x;
            Vt[(dc * 4 + 1) * FP + j] = v.y;
            Vt[(dc * 4 + 2) * FP + j] = v.z;
            Vt[(dc * 4 + 3) * FP + j] = v.w;
        }
        __syncthreads();

        #pragma unroll
        for (int ni = 0; ni < 8; ni++) {
            sac[ni][0] *= 0.125f; sac[ni][1] *= 0.125f;
            sac[ni][2] *= 0.125f; sac[ni][3] *= 0.125f;
        }
        if (jt == it) {
            #pragma unroll
            for (int ni = 0; ni < 8; ni++) {
                int cb = ni * 8 + 2 * tq;
                int r0 = wm + g, r1 = wm + g + 8;
                if (cb     > r0) sac[ni][0] = -1e30f;
                if (cb + 1 > r0) sac[ni][1] = -1e30f;
                if (cb     > r1) sac[ni][2] = -1e30f;
                if (cb + 1 > r1) sac[ni][3] = -1e30f;
            }
        }
        float a0 = -1e30f, a1 = -1e30f;
        #pragma unroll
        for (int ni = 0; ni < 8; ni++) {
            a0 = fmaxf(a0, fmaxf(sac[ni][0], sac[ni][1]));
            a1 = fmaxf(a1, fmaxf(sac[ni][2], sac[ni][3]));
        }
        a0 = fmaxf(a0, __shfl_xor_sync(0xffffffffu, a0, 1));
        a0 = fmaxf(a0, __shfl_xor_sync(0xffffffffu, a0, 2));
        a1 = fmaxf(a1, __shfl_xor_sync(0xffffffffu, a1, 1));
        a1 = fmaxf(a1, __shfl_xor_sync(0xffffffffu, a1, 2));
        float mn0 = fmaxf(m0, a0), mn1 = fmaxf(m1, a1);
        float al0 = __expf(m0 - mn0), al1 = __expf(m1 - mn1);
        m0 = mn0; m1 = mn1;
        l0 *= al0; l1 *= al1;
        #pragma unroll
        for (int ni = 0; ni < 8; ni++) {
            oac[ni][0] *= al0; oac[ni][1] *= al0;
            oac[ni][2] *= al1; oac[ni][3] *= al1;
        }
        float s0 = 0.f, s1 = 0.f;
        #pragma unroll
        for (int ni = 0; ni < 8; ni++) {
            float p0 = tf32r(__expf(sac[ni][0] - mn0));
            float p1 = tf32r(__expf(sac[ni][1] - mn0));
            float p2 = tf32r(__expf(sac[ni][2] - mn1));
            float p3 = tf32r(__expf(sac[ni][3] - mn1));
            s0 += p0 + p1; s1 += p2 + p3;
            int cb = ni * 8 + 2 * tq;
            float2 w0 = {p0, p1}, w1 = {p2, p3};
            *(float2*)&Ps[(wm + g) * FP + cb]     = w0;
            *(float2*)&Ps[(wm + g + 8) * FP + cb] = w1;
        }
        s0 += __shfl_xor_sync(0xffffffffu, s0, 1);
        s0 += __shfl_xor_sync(0xffffffffu, s0, 2);
        s1 += __shfl_xor_sync(0xffffffffu, s1, 1);
        s1 += __shfl_xor_sync(0xffffffffu, s1, 2);
        l0 += s0; l1 += s1;
        __syncwarp();

        #pragma unroll
        for (int kk = 0; kk < 8; kk++) {
            uint32_t pf[4];
            int c = kk * 2 + acb;
            ldsm4(pf, sbP + (uint32_t)((wm + arow) * FP + c * 4) * 4);
            #pragma unroll
            for (int nd = 0; nd < 8; nd++) {
                uint32_t b0 = __float_as_uint(Vt[(nd * 8 + g) * FP + kk * 8 + tq]);
                uint32_t b1 = __float_as_uint(Vt[(nd * 8 + g) * FP + kk * 8 + tq + 4]);
                mma_tf32(oac[nd], pf, b0, b1);
            }
        }
        __syncthreads();
    }

    float inv0 = 1.f / l0, inv1 = 1.f / l1;
    __half* od = xr + (size_t)(b * T_ + it * 64 + wm + g) * E_ + h * HD;
    #pragma unroll
    for (int nd = 0; nd < 8; nd++) {
        int cb = nd * 8 + 2 * tq;
        __half2 v0 = __floats2half2_rn(oac[nd][0] * inv0, oac[nd][1] * inv0);
        __half2 v1 = __floats2half2_rn(oac[nd][2] * inv1, oac[nd][3] * inv1);
        *(__half2*)(od + cb)                  = v0;
        *(__half2*)(od + (size_t)8 * E_ + cb) = v1;
    }
}

// ---------------- out = LayerNorm(in (+ res)) ----------------
__global__ void add_ln_kernel(const float* __restrict__ in,
                              const float* __restrict__ res,
                              const float* __restrict__ g,
                              const float* __restrict__ bb,
                              float* __restrict__ out,
                              __half* __restrict__ outr) {
    int row = blockIdx.x;
    int t = threadIdx.x;
    float4 v = ((const float4*)(in + (size_t)row * E_))[t];
    if (res) {
        float4 r = ((const float4*)(res + (size_t)row * E_))[t];
        v.x += r.x; v.y += r.y; v.z += r.z; v.w += r.w;
    }
    float s  = v.x + v.y + v.z + v.w;
    float s2 = v.x * v.x + v.y * v.y + v.z * v.z + v.w * v.w;

    __shared__ float sh[16];
    s = warpSum(s); s2 = warpSum(s2);
    int w = t >> 5, lane = t & 31;
    if (lane == 0) { sh[w] = s; sh[w + 8] = s2; }
    __syncthreads();
    if (w == 0) {
        float a  = (lane < 8) ? sh[lane] : 0.f;
        a = warpSum(a);
        float a2 = (lane < 8) ? sh[lane + 8] : 0.f;
        a2 = warpSum(a2);
        if (lane == 0) { sh[0] = a; sh[8] = a2; }
    }
    __syncthreads();
    float mean = sh[0] * (1.f / E_);
    float var  = sh[8] * (1.f / E_) - mean * mean;
    float rstd = rsqrtf(var + 1e-5f);

    float4 gv = ((const float4*)g)[t];
    float4 bv = ((const float4*)bb)[t];
    float4 o;
    o.x = (v.x - mean) * rstd * gv.x + bv.x;
    o.y = (v.y - mean) * rstd * gv.y + bv.y;
    o.z = (v.z - mean) * rstd * gv.z + bv.z;
    o.w = (v.w - mean) * rstd * gv.w + bv.w;
    ((float4*)(out + (size_t)row * E_))[t] = o;

    __half2 h0 = __floats2half2_rn(o.x, o.y);
    __half2 h1 = __floats2half2_rn(o.z, o.w);
    uint2 u; u.x = *(uint32_t*)&h0; u.y = *(uint32_t*)&h1;
    ((uint2*)(outr + (size_t)row * E_))[t] = u;
}

// ---------------- host launch ----------------
extern "C" void kernel_launch(void* const* d_in, const int* in_sizes, int n_in,
                              void* d_out, int out_size) {
    const int*   idx   = (const int*)  d_in[0];
    const float* tok   = (const float*)d_in[1];
    const float* pos   = (const float*)d_in[2];
    const float* Wq    = (const float*)d_in[3];
    const float* bq    = (const float*)d_in[4];
    const float* Wk    = (const float*)d_in[5];
    const float* bk    = (const float*)d_in[6];
    const float* Wv    = (const float*)d_in[7];
    const float* bv    = (const float*)d_in[8];
    const float* Wo    = (const float*)d_in[9];
    const float* bo    = (const float*)d_in[10];
    const float* W1    = (const float*)d_in[11];
    const float* b1    = (const float*)d_in[12];
    const float* W2    = (const float*)d_in[13];
    const float* b2    = (const float*)d_in[14];
    const float* ln1g  = (const float*)d_in[15];
    const float* ln1b  = (const float*)d_in[16];
    const float* ln2g  = (const float*)d_in[17];
    const float* ln2b  = (const float*)d_in[18];
    const float* lnfg  = (const float*)d_in[19];
    const float* lnfb  = (const float*)d_in[20];
    const float* Whead = (const float*)d_in[21];
    const float* bhead = (const float*)d_in[22];
    float* out = (float*)d_out;

    float *x, *qkv, *tmp, *bqkv;
    __half *xr, *ffr, *wt;
    cudaGetSymbolAddress((void**)&x,    g_x);
    cudaGetSymbolAddress((void**)&xr,   g_xr);
    cudaGetSymbolAddress((void**)&qkv,  g_qkv);
    cudaGetSymbolAddress((void**)&tmp,  g_tmp);
    cudaGetSymbolAddress((void**)&ffr,  g_ffr);
    cudaGetSymbolAddress((void**)&bqkv, g_bqkv);
    cudaGetSymbolAddress((void**)&wt,   g_wt);

    cudaFuncSetAttribute(h16_gemm_kernel<0,0>,
                         cudaFuncAttributeMaxDynamicSharedMemorySize, GSM);
    cudaFuncSetAttribute(h16_gemm_kernel<0,1>,
                         cudaFuncAttributeMaxDynamicSharedMemorySize, GSM);
    cudaFuncSetAttribute(h16_gemm_kernel<1,2>,
                         cudaFuncAttributeMaxDynamicSharedMemorySize, GSM);
    cudaFuncSetAttribute(flash_kernel,
                         cudaFuncAttributeMaxDynamicSharedMemorySize, FSMEM);

    tconv_kernel<<<dim3(E_ / 32,  E_ / 32,  L_), 256>>>(Wq, wt + OQKV,             E_, E_, 3 * SZ_EE);
    tconv_kernel<<<dim3(E_ / 32,  E_ / 32,  L_), 256>>>(Wk, wt + OQKV + SZ_EE,     E_, E_, 3 * SZ_EE);
    tconv_kernel<<<dim3(E_ / 32,  E_ / 32,  L_), 256>>>(Wv, wt + OQKV + 2 * SZ_EE, E_, E_, 3 * SZ_EE);
    tconv_kernel<<<dim3(E_ / 32,  E_ / 32,  L_), 256>>>(Wo, wt + OWO,  E_,  E_,  SZ_EE);
    tconv_kernel<<<dim3(FF_ / 32, E_ / 32,  L_), 256>>>(W1, wt + OW1,  E_,  FF_, (size_t)E_ * FF_);
    tconv_kernel<<<dim3(E_ / 32,  FF_ / 32, L_), 256>>>(W2, wt + OW2,  FF_, E_,  (size_t)E_ * FF_);
    tconv_kernel<<<dim3(V_ / 32,  E_ / 32,  1 ), 256>>>(Whead, wt + OHEAD, E_, V_, 0);
    pack_bias_kernel<<<dim3(12, L_), 256>>>(bq, bk, bv, bqkv);

    embed_kernel<<<BT, 256>>>(idx, tok, pos, x, xr);

    dim3 gQKV(E3 / 128, BT / 128);
    dim3 gEE(E_ / 128, BT / 128);
    dim3 gEF(FF_ / 128, BT / 128);
    dim3 gHead(V_ / 128, BT / 128);

    for (int l = 0; l < L_; l++) {
        h16_gemm_kernel<0,1><<<gQKV, 256, GSM>>>(
            xr, wt + OQKV + (size_t)l * 3 * SZ_EE, bqkv + l * E3,
            qkv, nullptr, BT, E3, E_);

        flash_kernel<<<dim3(16, B_ * H_), 128, FSMEM>>>(qkv, xr);

        h16_gemm_kernel<0,0><<<gEE, 256, GSM>>>(
            xr, wt + OWO + (size_t)l * SZ_EE, bo + l * E_,
            tmp, nullptr, BT, E_, E_);
        add_ln_kernel<<<BT, 256>>>(x, tmp, ln1g + l * E_, ln1b + l * E_, x, xr);

        h16_gemm_kernel<1,2><<<gEF, 256, GSM>>>(
            xr, wt + OW1 + (size_t)l * E_ * FF_, b1 + l * FF_,
            nullptr, ffr, BT, FF_, E_);
        h16_gemm_kernel<0,0><<<gEE, 256, GSM>>>(
            ffr, wt + OW2 + (size_t)l * E_ * FF_, b2 + l * E_,
            tmp, nullptr, BT, E_, FF_);
        add_ln_kernel<<<BT, 256>>>(x, tmp, ln2g + l * E_, ln2b + l * E_, x, xr);
    }

    add_ln_kernel<<<BT, 256>>>(x, nullptr, lnfg, lnfb, x, xr);
    h16_gemm_kernel<0,0><<<gHead, 256, GSM>>>(
        xr, wt + OHEAD, bhead, out, nullptr, BT, V_, E_);
}